// round 1
// baseline (speedup 1.0000x reference)
#include <cuda_runtime.h>

#define N_SRNA 20000
#define N_MRNA 100000
#define HID    128
#define E_S2M  1000000
#define E_M2M  2000000
#define E_LBL  500000

// ------------------------- scratch (module-static, no runtime alloc) ----------
__device__ float g_xwf  [N_MRNA*HID];
__device__ float g_xwr2 [N_MRNA*HID];
__device__ float g_basem[N_MRNA*HID];
__device__ float g_aggm [N_MRNA*HID];
__device__ float g_gcnf [N_MRNA*HID];
__device__ float g_gcnr [N_MRNA*HID];
__device__ float g_xm0  [N_MRNA*HID];
__device__ float g_xm1  [N_MRNA*HID];
__device__ float g_bases[N_SRNA*HID];
__device__ float g_aggs [N_SRNA*HID];
__device__ float g_xs0  [N_SRNA*HID];
__device__ float g_xs1  [N_SRNA*HID];
__device__ float g_cinvm[N_MRNA];
__device__ float g_cinvs[N_SRNA];
__device__ float g_dinvf[N_MRNA];
__device__ float g_dinvr[N_MRNA];

// ------------------------- helpers -------------------------------------------
__device__ __forceinline__ void red_add_v4(float* p, float4 v) {
    asm volatile("red.global.add.v4.f32 [%0], {%1,%2,%3,%4};"
                 :: "l"(p), "f"(v.x), "f"(v.y), "f"(v.z), "f"(v.w) : "memory");
}

// ------------------------- degree / count kernels -----------------------------
__global__ void count_k(const int* __restrict__ idx, float* __restrict__ cnt, int E) {
    int i = blockIdx.x * blockDim.x + threadIdx.x;
    int stride = gridDim.x * blockDim.x;
    for (; i < E; i += stride) atomicAdd(&cnt[idx[i]], 1.0f);
}

__global__ void finalize_cinv_k(float* __restrict__ c, int n) {
    int i = blockIdx.x * blockDim.x + threadIdx.x;
    if (i < n) c[i] = 1.0f / fmaxf(c[i], 1.0f);
}

__global__ void finalize_dinv_k(float* __restrict__ c, int n) {
    int i = blockIdx.x * blockDim.x + threadIdx.x;
    if (i < n) c[i] = rsqrtf(c[i] + 1.0f);
}

// ------------------------- GEMM core: Y = (X .* rowscale) @ W -----------------
// X [n,128] row-major, W [128,128] row-major (out[c] = sum_k x[k] * W[k*128+c])
// block = 256 threads, tile = 128 rows x 128 cols, 8x8 microtile per thread.
__device__ __forceinline__ void gemm_core(
    const float* __restrict__ X, const float* __restrict__ rowscale,
    const float* __restrict__ W, int n, int row0,
    float (*Xs)[33], float (*Ws)[128], float acc[8][8])
{
    int tid = threadIdx.x;
#pragma unroll
    for (int i = 0; i < 8; i++)
#pragma unroll
        for (int j = 0; j < 8; j++) acc[i][j] = 0.0f;

    int tr = tid >> 4, tc = tid & 15;

    for (int kb = 0; kb < 4; kb++) {
        // X tile: 128 rows x 32 k's
#pragma unroll
        for (int u = 0; u < 4; u++) {
            int lin = tid + u * 256;           // 0..1023 float4 slots
            int r   = lin >> 3;                // 0..127
            int c4  = (lin & 7) * 4;           // 0..28
            int gr  = row0 + r;
            float4 v = make_float4(0.f, 0.f, 0.f, 0.f);
            if (gr < n) {
                v = *(const float4*)&X[(size_t)gr * HID + kb * 32 + c4];
                if (rowscale) {
                    float s = rowscale[gr];
                    v.x *= s; v.y *= s; v.z *= s; v.w *= s;
                }
            }
            Xs[r][c4 + 0] = v.x; Xs[r][c4 + 1] = v.y;
            Xs[r][c4 + 2] = v.z; Xs[r][c4 + 3] = v.w;
        }
        // W chunk: 32 k's x 128 cols
#pragma unroll
        for (int u = 0; u < 4; u++) {
            int lin = tid + u * 256;
            int r   = lin >> 5;                // 0..31
            int c4  = (lin & 31) * 4;
            float4 v = *(const float4*)&W[(size_t)(kb * 32 + r) * HID + c4];
            *(float4*)&Ws[r][c4] = v;
        }
        __syncthreads();
#pragma unroll 8
        for (int kk = 0; kk < 32; kk++) {
            float a[8];
#pragma unroll
            for (int i = 0; i < 8; i++) a[i] = Xs[tr * 8 + i][kk];
            float4 b0 = *(const float4*)&Ws[kk][tc * 8];
            float4 b1 = *(const float4*)&Ws[kk][tc * 8 + 4];
            float b[8] = {b0.x, b0.y, b0.z, b0.w, b1.x, b1.y, b1.z, b1.w};
#pragma unroll
            for (int i = 0; i < 8; i++)
#pragma unroll
                for (int j = 0; j < 8; j++)
                    acc[i][j] = fmaf(a[i], b[j], acc[i][j]);
        }
        __syncthreads();
    }
}

__global__ __launch_bounds__(256) void gemm_plain_k(
    const float* __restrict__ X, const float* __restrict__ W,
    float* __restrict__ Y, int n)
{
    __shared__ float Xs[128][33];
    __shared__ float Ws[32][128];
    float acc[8][8];
    int row0 = blockIdx.x * 128;
    gemm_core(X, nullptr, W, n, row0, Xs, Ws, acc);
    int tid = threadIdx.x, tr = tid >> 4, tc = tid & 15;
#pragma unroll
    for (int i = 0; i < 8; i++) {
        int r = row0 + tr * 8 + i;
        if (r >= n) continue;
#pragma unroll
        for (int g = 0; g < 2; g++) {
            float4 v = make_float4(acc[i][g*4+0], acc[i][g*4+1], acc[i][g*4+2], acc[i][g*4+3]);
            *(float4*)&Y[(size_t)r * HID + tc * 8 + g * 4] = v;
        }
    }
}

// m_new = relu( (agg .* cinv)@Wl + (bl+bf+br) + base + gcnf + df^2*xwf + gcnr + dr^2*xwr )
__global__ __launch_bounds__(256) void gemm_combine_m_k(
    const float* __restrict__ AGG, const float* __restrict__ cinv,
    const float* __restrict__ Wl,
    const float* __restrict__ bl, const float* __restrict__ bf, const float* __restrict__ br,
    const float* __restrict__ base, const float* __restrict__ gcnf,
    const float* __restrict__ xwf,  const float* __restrict__ dinvf,
    const float* __restrict__ gcnr, const float* __restrict__ xwr,
    const float* __restrict__ dinvr,
    float* __restrict__ Y, int n)
{
    __shared__ float Xs[128][33];
    __shared__ float Ws[32][128];
    float acc[8][8];
    int row0 = blockIdx.x * 128;
    gemm_core(AGG, cinv, Wl, n, row0, Xs, Ws, acc);
    int tid = threadIdx.x, tr = tid >> 4, tc = tid & 15;
    int c0 = tc * 8;
    float bias[8];
#pragma unroll
    for (int j = 0; j < 8; j++) bias[j] = bl[c0 + j] + bf[c0 + j] + br[c0 + j];
#pragma unroll
    for (int i = 0; i < 8; i++) {
        int r = row0 + tr * 8 + i;
        if (r >= n) continue;
        float df = dinvf[r], dr = dinvr[r];
        float df2 = df * df, dr2 = dr * dr;
        size_t off = (size_t)r * HID + c0;
#pragma unroll
        for (int g = 0; g < 2; g++) {
            float4 vb  = *(const float4*)&base[off + g * 4];
            float4 vgf = *(const float4*)&gcnf[off + g * 4];
            float4 vxf = *(const float4*)&xwf [off + g * 4];
            float4 vgr = *(const float4*)&gcnr[off + g * 4];
            float4 vxr = *(const float4*)&xwr [off + g * 4];
            float4 o;
            o.x = acc[i][g*4+0] + bias[g*4+0] + vb.x + vgf.x + df2*vxf.x + vgr.x + dr2*vxr.x;
            o.y = acc[i][g*4+1] + bias[g*4+1] + vb.y + vgf.y + df2*vxf.y + vgr.y + dr2*vxr.y;
            o.z = acc[i][g*4+2] + bias[g*4+2] + vb.z + vgf.z + df2*vxf.z + vgr.z + dr2*vxr.z;
            o.w = acc[i][g*4+3] + bias[g*4+3] + vb.w + vgf.w + df2*vxf.w + vgr.w + dr2*vxr.w;
            o.x = fmaxf(o.x, 0.f); o.y = fmaxf(o.y, 0.f);
            o.z = fmaxf(o.z, 0.f); o.w = fmaxf(o.w, 0.f);
            *(float4*)&Y[off + g * 4] = o;
        }
    }
}

// s_new = relu( (agg .* cinv)@Wl + bl + base )
__global__ __launch_bounds__(256) void gemm_combine_s_k(
    const float* __restrict__ AGG, const float* __restrict__ cinv,
    const float* __restrict__ Wl, const float* __restrict__ bl,
    const float* __restrict__ base,
    float* __restrict__ Y, int n)
{
    __shared__ float Xs[128][33];
    __shared__ float Ws[32][128];
    float acc[8][8];
    int row0 = blockIdx.x * 128;
    gemm_core(AGG, cinv, Wl, n, row0, Xs, Ws, acc);
    int tid = threadIdx.x, tr = tid >> 4, tc = tid & 15;
    int c0 = tc * 8;
    float bias[8];
#pragma unroll
    for (int j = 0; j < 8; j++) bias[j] = bl[c0 + j];
#pragma unroll
    for (int i = 0; i < 8; i++) {
        int r = row0 + tr * 8 + i;
        if (r >= n) continue;
        size_t off = (size_t)r * HID + c0;
#pragma unroll
        for (int g = 0; g < 2; g++) {
            float4 vb = *(const float4*)&base[off + g * 4];
            float4 o;
            o.x = fmaxf(acc[i][g*4+0] + bias[g*4+0] + vb.x, 0.f);
            o.y = fmaxf(acc[i][g*4+1] + bias[g*4+1] + vb.y, 0.f);
            o.z = fmaxf(acc[i][g*4+2] + bias[g*4+2] + vb.z, 0.f);
            o.w = fmaxf(acc[i][g*4+3] + bias[g*4+3] + vb.w, 0.f);
            *(float4*)&Y[off + g * 4] = o;
        }
    }
}

// ------------------------- scatter kernels ------------------------------------
// AGG[dst[e]] += X[src[e]]   (one warp per edge, float4 per lane, vector RED)
__global__ void sage_scatter_k(const int* __restrict__ src, const int* __restrict__ dst,
                               const float* __restrict__ X, float* __restrict__ AGG, int E)
{
    int e = (blockIdx.x * blockDim.x + threadIdx.x) >> 5;
    if (e >= E) return;
    int lane = threadIdx.x & 31;
    int s = __ldg(&src[e]);
    int d = __ldg(&dst[e]);
    float4 v = *(const float4*)&X[(size_t)s * HID + lane * 4];
    red_add_v4(&AGG[(size_t)d * HID + lane * 4], v);
}

// Both GCN directions from one edge read:
//   OUTF[d] += dinvf[s]*dinvf[d] * XWF[s]
//   OUTR[s] += dinvr[s]*dinvr[d] * XWR[d]
__global__ void gcn_dual_scatter_k(const int* __restrict__ src, const int* __restrict__ dst,
                                   const float* __restrict__ XWF, const float* __restrict__ XWR,
                                   const float* __restrict__ dinvf, const float* __restrict__ dinvr,
                                   float* __restrict__ OUTF, float* __restrict__ OUTR, int E)
{
    int e = (blockIdx.x * blockDim.x + threadIdx.x) >> 5;
    if (e >= E) return;
    int lane = threadIdx.x & 31;
    int s = __ldg(&src[e]);
    int d = __ldg(&dst[e]);
    float nf = __ldg(&dinvf[s]) * __ldg(&dinvf[d]);
    float nr = __ldg(&dinvr[s]) * __ldg(&dinvr[d]);
    float4 vf = *(const float4*)&XWF[(size_t)s * HID + lane * 4];
    vf.x *= nf; vf.y *= nf; vf.z *= nf; vf.w *= nf;
    red_add_v4(&OUTF[(size_t)d * HID + lane * 4], vf);
    float4 vr = *(const float4*)&XWR[(size_t)d * HID + lane * 4];
    vr.x *= nr; vr.y *= nr; vr.z *= nr; vr.w *= nr;
    red_add_v4(&OUTR[(size_t)s * HID + lane * 4], vr);
}

// ------------------------- classifier -----------------------------------------
__global__ void classifier_k(const int* __restrict__ ls, const int* __restrict__ ld,
                             const float* __restrict__ XS, const float* __restrict__ XM,
                             float* __restrict__ out, int E)
{
    int e = (blockIdx.x * blockDim.x + threadIdx.x) >> 5;
    if (e >= E) return;
    int lane = threadIdx.x & 31;
    int s = __ldg(&ls[e]);
    int d = __ldg(&ld[e]);
    float4 a = *(const float4*)&XS[(size_t)s * HID + lane * 4];
    float4 b = *(const float4*)&XM[(size_t)d * HID + lane * 4];
    float p = a.x * b.x + a.y * b.y + a.z * b.z + a.w * b.w;
#pragma unroll
    for (int o = 16; o > 0; o >>= 1) p += __shfl_xor_sync(0xffffffffu, p, o);
    if (lane == 0) out[e] = p;
}

// ------------------------- launch ---------------------------------------------
extern "C" void kernel_launch(void* const* d_in, const int* in_sizes, int n_in,
                              void* d_out, int out_size)
{
    const int*   s2m_src   = (const int*)d_in[0];
    const int*   s2m_dst   = (const int*)d_in[1];
    const int*   m2m_src   = (const int*)d_in[2];
    const int*   m2m_dst   = (const int*)d_in[3];
    const int*   label_src = (const int*)d_in[4];
    const int*   label_dst = (const int*)d_in[5];
    const float* srna_emb  = (const float*)d_in[6];
    const float* mrna_emb  = (const float*)d_in[7];
    const float* sage_s2m_Wl = (const float*)d_in[8];
    const float* sage_s2m_bl = (const float*)d_in[9];
    const float* sage_s2m_Wr = (const float*)d_in[10];
    const float* sage_rev_Wl = (const float*)d_in[11];
    const float* sage_rev_bl = (const float*)d_in[12];
    const float* sage_rev_Wr = (const float*)d_in[13];
    const float* gcn_m2m_W   = (const float*)d_in[14];
    const float* gcn_m2m_b   = (const float*)d_in[15];
    const float* gcn_rev_W   = (const float*)d_in[16];
    const float* gcn_rev_b   = (const float*)d_in[17];
    float* out = (float*)d_out;

    float *xwf, *xwr, *basem, *aggm, *gcnf, *gcnr, *xm0, *xm1;
    float *bases, *aggs, *xs0, *xs1, *cinvm, *cinvs, *dinvf, *dinvr;
    cudaGetSymbolAddress((void**)&xwf,   g_xwf);
    cudaGetSymbolAddress((void**)&xwr,   g_xwr2);
    cudaGetSymbolAddress((void**)&basem, g_basem);
    cudaGetSymbolAddress((void**)&aggm,  g_aggm);
    cudaGetSymbolAddress((void**)&gcnf,  g_gcnf);
    cudaGetSymbolAddress((void**)&gcnr,  g_gcnr);
    cudaGetSymbolAddress((void**)&xm0,   g_xm0);
    cudaGetSymbolAddress((void**)&xm1,   g_xm1);
    cudaGetSymbolAddress((void**)&bases, g_bases);
    cudaGetSymbolAddress((void**)&aggs,  g_aggs);
    cudaGetSymbolAddress((void**)&xs0,   g_xs0);
    cudaGetSymbolAddress((void**)&xs1,   g_xs1);
    cudaGetSymbolAddress((void**)&cinvm, g_cinvm);
    cudaGetSymbolAddress((void**)&cinvs, g_cinvs);
    cudaGetSymbolAddress((void**)&dinvf, g_dinvf);
    cudaGetSymbolAddress((void**)&dinvr, g_dinvr);

    // ---- degrees (layer-invariant) ----
    cudaMemsetAsync(cinvm, 0, (size_t)N_MRNA * sizeof(float));
    cudaMemsetAsync(cinvs, 0, (size_t)N_SRNA * sizeof(float));
    cudaMemsetAsync(dinvf, 0, (size_t)N_MRNA * sizeof(float));
    cudaMemsetAsync(dinvr, 0, (size_t)N_MRNA * sizeof(float));
    count_k<<<2048, 256>>>(s2m_dst, cinvm, E_S2M);
    count_k<<<2048, 256>>>(s2m_src, cinvs, E_S2M);
    count_k<<<2048, 256>>>(m2m_dst, dinvf, E_M2M);
    count_k<<<2048, 256>>>(m2m_src, dinvr, E_M2M);
    finalize_cinv_k<<<(N_MRNA + 255) / 256, 256>>>(cinvm, N_MRNA);
    finalize_cinv_k<<<(N_SRNA + 255) / 256, 256>>>(cinvs, N_SRNA);
    finalize_dinv_k<<<(N_MRNA + 255) / 256, 256>>>(dinvf, N_MRNA);
    finalize_dinv_k<<<(N_MRNA + 255) / 256, 256>>>(dinvr, N_MRNA);

    const float* xs = srna_emb;
    const float* xm = mrna_emb;
    float* xm_bufs[2] = {xm0, xm1};
    float* xs_bufs[2] = {xs0, xs1};

    const int gm = (N_MRNA + 127) / 128;
    const int gs = (N_SRNA + 127) / 128;
    const int sage_blocks = (E_S2M * 32 + 255) / 256;
    const int gcn_blocks  = (E_M2M * 32 + 255) / 256;

    for (int l = 0; l < 2; l++) {
        const float* Wf  = gcn_m2m_W   + (size_t)l * HID * HID;
        const float* bfp = gcn_m2m_b   + (size_t)l * HID;
        const float* Wg  = gcn_rev_W   + (size_t)l * HID * HID;
        const float* brp = gcn_rev_b   + (size_t)l * HID;
        const float* sWl = sage_s2m_Wl + (size_t)l * HID * HID;
        const float* sbl = sage_s2m_bl + (size_t)l * HID;
        const float* sWr = sage_s2m_Wr + (size_t)l * HID * HID;
        const float* rWl = sage_rev_Wl + (size_t)l * HID * HID;
        const float* rbl = sage_rev_bl + (size_t)l * HID;
        const float* rWr = sage_rev_Wr + (size_t)l * HID * HID;

        cudaMemsetAsync(aggm, 0, (size_t)N_MRNA * HID * sizeof(float));
        cudaMemsetAsync(aggs, 0, (size_t)N_SRNA * HID * sizeof(float));
        cudaMemsetAsync(gcnf, 0, (size_t)N_MRNA * HID * sizeof(float));
        cudaMemsetAsync(gcnr, 0, (size_t)N_MRNA * HID * sizeof(float));

        gemm_plain_k<<<gm, 256>>>(xm, Wf,  xwf,   N_MRNA);
        gemm_plain_k<<<gm, 256>>>(xm, Wg,  xwr,   N_MRNA);
        gemm_plain_k<<<gm, 256>>>(xm, sWr, basem, N_MRNA);
        gemm_plain_k<<<gs, 256>>>(xs, rWr, bases, N_SRNA);

        sage_scatter_k<<<sage_blocks, 256>>>(s2m_src, s2m_dst, xs, aggm, E_S2M);
        sage_scatter_k<<<sage_blocks, 256>>>(s2m_dst, s2m_src, xm, aggs, E_S2M);
        gcn_dual_scatter_k<<<gcn_blocks, 256>>>(m2m_src, m2m_dst, xwf, xwr,
                                                dinvf, dinvr, gcnf, gcnr, E_M2M);

        gemm_combine_m_k<<<gm, 256>>>(aggm, cinvm, sWl, sbl, bfp, brp,
                                      basem, gcnf, xwf, dinvf, gcnr, xwr, dinvr,
                                      xm_bufs[l], N_MRNA);
        gemm_combine_s_k<<<gs, 256>>>(aggs, cinvs, rWl, rbl, bases,
                                      xs_bufs[l], N_SRNA);

        xm = xm_bufs[l];
        xs = xs_bufs[l];
    }

    classifier_k<<<(E_LBL * 32 + 255) / 256, 256>>>(label_src, label_dst, xs, xm, out, E_LBL);
}

// round 4
// speedup vs baseline: 1.5907x; 1.5907x over previous
#include <cuda_runtime.h>

#define N_SRNA 20000
#define N_MRNA 100000
#define HID    128
#define E_S2M  1000000
#define E_M2M  2000000
#define E_LBL  500000

// ------------------------- scratch (module-static) ----------------------------
__device__ float g_aggm[N_MRNA*HID];   // SAGE agg -> mRNA
__device__ float g_aggf[N_MRNA*HID];   // GCN fwd agg (incl self-loop, pre-normed)
__device__ float g_aggr[N_MRNA*HID];   // GCN rev agg
__device__ float g_xm0 [N_MRNA*HID];
__device__ float g_xm1 [N_MRNA*HID];
__device__ float g_aggs[N_SRNA*HID];   // SAGE agg -> sRNA
__device__ float g_xs0 [N_SRNA*HID];
__device__ float g_xs1 [N_SRNA*HID];

__device__ float g_cinvm[N_MRNA];
__device__ float g_cinvs[N_SRNA];
__device__ float g_dinvf[N_MRNA];
__device__ float g_dinvr[N_MRNA];

// CSR structures (counting sort per call)
__device__ int g_cntA[N_MRNA];  __device__ int g_offA[N_MRNA+1];  __device__ int g_curA[N_MRNA];
__device__ int g_cntB[N_SRNA];  __device__ int g_offB[N_SRNA+1];  __device__ int g_curB[N_SRNA];
__device__ int g_cntC[N_MRNA];  __device__ int g_offC[N_MRNA+1];  __device__ int g_curC[N_MRNA];
__device__ int g_cntD[N_MRNA];  __device__ int g_offD[N_MRNA+1];  __device__ int g_curD[N_MRNA];
__device__ int g_adjA[E_S2M];   // s2m by dst -> src ids
__device__ int g_adjB[E_S2M];   // s2m by src -> dst ids
__device__ int g_adjC[E_M2M];   // m2m by dst -> src ids
__device__ int g_adjD[E_M2M];   // m2m by src -> dst ids

// ------------------------- counting -------------------------------------------
__global__ void count_int_k(const int* __restrict__ idx, int* __restrict__ cnt, int E) {
    int i = blockIdx.x * blockDim.x + threadIdx.x;
    int stride = gridDim.x * blockDim.x;
    for (; i < E; i += stride) atomicAdd(&cnt[idx[i]], 1);
}

__global__ void finalize_cinv_k(const int* __restrict__ cnt, float* __restrict__ o, int n) {
    int i = blockIdx.x * blockDim.x + threadIdx.x;
    if (i < n) o[i] = 1.0f / fmaxf((float)cnt[i], 1.0f);
}

__global__ void finalize_dinv_k(const int* __restrict__ cnt, float* __restrict__ o, int n) {
    int i = blockIdx.x * blockDim.x + threadIdx.x;
    if (i < n) o[i] = rsqrtf((float)cnt[i] + 1.0f);
}

// ------------------------- 4-way exclusive scan (one block per array) ----------
__device__ void scan_body(const int* __restrict__ cnt, int* __restrict__ off, int n) {
    __shared__ int wsum[32];
    __shared__ int s_carry;
    int tid = threadIdx.x, lane = tid & 31, wid = tid >> 5;
    if (tid == 0) { s_carry = 0; off[0] = 0; }
    __syncthreads();
    for (int base = 0; base < n; base += 4096) {
        int i0 = base + tid * 4;
        int v0 = (i0 + 0 < n) ? cnt[i0 + 0] : 0;
        int v1 = (i0 + 1 < n) ? cnt[i0 + 1] : 0;
        int v2 = (i0 + 2 < n) ? cnt[i0 + 2] : 0;
        int v3 = (i0 + 3 < n) ? cnt[i0 + 3] : 0;
        int t = v0 + v1 + v2 + v3;
        int x = t;
#pragma unroll
        for (int d = 1; d < 32; d <<= 1) {
            int y = __shfl_up_sync(0xffffffffu, x, d);
            if (lane >= d) x += y;
        }
        if (lane == 31) wsum[wid] = x;
        __syncthreads();
        if (wid == 0) {
            int z = wsum[lane];
#pragma unroll
            for (int d = 1; d < 32; d <<= 1) {
                int y = __shfl_up_sync(0xffffffffu, z, d);
                if (lane >= d) z += y;
            }
            wsum[lane] = z;
        }
        __syncthreads();
        int warpoff = (wid == 0) ? 0 : wsum[wid - 1];
        int excl = warpoff + (x - t) + s_carry;
        if (i0 + 0 < n) off[i0 + 1] = excl + v0;
        if (i0 + 1 < n) off[i0 + 2] = excl + v0 + v1;
        if (i0 + 2 < n) off[i0 + 3] = excl + v0 + v1 + v2;
        if (i0 + 3 < n) off[i0 + 4] = excl + v0 + v1 + v2 + v3;
        __syncthreads();
        if (tid == 0) s_carry += wsum[31];
        __syncthreads();
    }
}

__global__ __launch_bounds__(1024) void scan4_k(
    const int* c0, int* o0, int n0, const int* c1, int* o1, int n1,
    const int* c2, int* o2, int n2, const int* c3, int* o3, int n3)
{
    switch (blockIdx.x) {
        case 0: scan_body(c0, o0, n0); break;
        case 1: scan_body(c1, o1, n1); break;
        case 2: scan_body(c2, o2, n2); break;
        default: scan_body(c3, o3, n3); break;
    }
}

// ------------------------- CSR fill --------------------------------------------
__global__ void fill_k(const int* __restrict__ key, const int* __restrict__ val,
                       const int* __restrict__ off, int* __restrict__ cur,
                       int* __restrict__ adj, int E)
{
    int i = blockIdx.x * blockDim.x + threadIdx.x;
    int stride = gridDim.x * blockDim.x;
    for (; i < E; i += stride) {
        int k = key[i];
        int pos = off[k] + atomicAdd(&cur[k], 1);
        adj[pos] = val[i];
    }
}

// ------------------------- warp-per-node gather --------------------------------
template<bool WEIGHTED, bool SELF>
__global__ __launch_bounds__(256) void gather_k(
    const int* __restrict__ off, const int* __restrict__ adj,
    const float* __restrict__ X, const float* __restrict__ dinv,
    float* __restrict__ OUT, int n)
{
    int node = (blockIdx.x * blockDim.x + threadIdx.x) >> 5;
    if (node >= n) return;
    int lane = threadIdx.x & 31;
    int beg = off[node], end = off[node + 1];

    float4 selfv = make_float4(0.f, 0.f, 0.f, 0.f);
    float dd = 0.f;
    if (SELF) {
        dd = __ldg(&dinv[node]);
        selfv = *(const float4*)&X[(size_t)node * HID + lane * 4];
    }

    float4 acc = make_float4(0.f, 0.f, 0.f, 0.f);
    for (int base = beg; base < end; base += 32) {
        int m = end - base;
        int nb = 0; float w = 0.f;
        if (lane < m) {
            nb = __ldg(&adj[base + lane]);
            if (WEIGHTED) w = __ldg(&dinv[nb]);
        }
        int iters = m < 32 ? m : 32;
#pragma unroll 4
        for (int j = 0; j < iters; j++) {
            int id = __shfl_sync(0xffffffffu, nb, j);
            float wj = WEIGHTED ? __shfl_sync(0xffffffffu, w, j) : 1.0f;
            float4 v = *(const float4*)&X[(size_t)id * HID + lane * 4];
            acc.x = fmaf(wj, v.x, acc.x);
            acc.y = fmaf(wj, v.y, acc.y);
            acc.z = fmaf(wj, v.z, acc.z);
            acc.w = fmaf(wj, v.w, acc.w);
        }
    }
    if (SELF) {
        acc.x = dd * (acc.x + dd * selfv.x);
        acc.y = dd * (acc.y + dd * selfv.y);
        acc.z = dd * (acc.z + dd * selfv.z);
        acc.w = dd * (acc.w + dd * selfv.w);
    }
    *(float4*)&OUT[(size_t)node * HID + lane * 4] = acc;
}

// ------------------------- GEMM core (accumulating) ----------------------------
// acc += (X[row0:row0+128] .* rowscale) @ W,  X [n,128], W [128,128] row-major
__device__ __forceinline__ void gemm_core_acc(
    const float* __restrict__ X, const float* __restrict__ rowscale,
    const float* __restrict__ W, int n, int row0,
    float (*Xs)[33], float (*Ws)[128], float acc[8][8])
{
    int tid = threadIdx.x;
    int tr = tid >> 4, tc = tid & 15;
    for (int kb = 0; kb < 4; kb++) {
#pragma unroll
        for (int u = 0; u < 4; u++) {
            int lin = tid + u * 256;
            int r   = lin >> 3;
            int c4  = (lin & 7) * 4;
            int gr  = row0 + r;
            float4 v = make_float4(0.f, 0.f, 0.f, 0.f);
            if (gr < n) {
                v = *(const float4*)&X[(size_t)gr * HID + kb * 32 + c4];
                if (rowscale) {
                    float s = rowscale[gr];
                    v.x *= s; v.y *= s; v.z *= s; v.w *= s;
                }
            }
            Xs[r][c4 + 0] = v.x; Xs[r][c4 + 1] = v.y;
            Xs[r][c4 + 2] = v.z; Xs[r][c4 + 3] = v.w;
        }
#pragma unroll
        for (int u = 0; u < 4; u++) {
            int lin = tid + u * 256;
            int r   = lin >> 5;
            int c4  = (lin & 31) * 4;
            *(float4*)&Ws[r][c4] = *(const float4*)&W[(size_t)(kb * 32 + r) * HID + c4];
        }
        __syncthreads();
#pragma unroll 8
        for (int kk = 0; kk < 32; kk++) {
            float a[8];
#pragma unroll
            for (int i = 0; i < 8; i++) a[i] = Xs[tr * 8 + i][kk];
            float4 b0 = *(const float4*)&Ws[kk][tc * 8];
            float4 b1 = *(const float4*)&Ws[kk][tc * 8 + 4];
            float b[8] = {b0.x, b0.y, b0.z, b0.w, b1.x, b1.y, b1.z, b1.w};
#pragma unroll
            for (int i = 0; i < 8; i++)
#pragma unroll
                for (int j = 0; j < 8; j++)
                    acc[i][j] = fmaf(a[i], b[j], acc[i][j]);
        }
        __syncthreads();
    }
}

// Y = relu( (X0.*rs0)@W0 + X1@W1 + X2@W2 + X3@W3 + bias )
__global__ __launch_bounds__(256) void gemm4_relu_k(
    const float* __restrict__ X0, const float* __restrict__ rs0, const float* __restrict__ W0,
    const float* __restrict__ X1, const float* __restrict__ W1,
    const float* __restrict__ X2, const float* __restrict__ W2,
    const float* __restrict__ X3, const float* __restrict__ W3,
    const float* __restrict__ b0, const float* __restrict__ b1, const float* __restrict__ b2,
    float* __restrict__ Y, int n)
{
    __shared__ float Xs[128][33];
    __shared__ float Ws[32][128];
    float acc[8][8];
#pragma unroll
    for (int i = 0; i < 8; i++)
#pragma unroll
        for (int j = 0; j < 8; j++) acc[i][j] = 0.0f;
    int row0 = blockIdx.x * 128;
    gemm_core_acc(X0, rs0,     W0, n, row0, Xs, Ws, acc);
    gemm_core_acc(X1, nullptr, W1, n, row0, Xs, Ws, acc);
    gemm_core_acc(X2, nullptr, W2, n, row0, Xs, Ws, acc);
    gemm_core_acc(X3, nullptr, W3, n, row0, Xs, Ws, acc);
    int tid = threadIdx.x, tr = tid >> 4, tc = tid & 15;
    int c0 = tc * 8;
    float bias[8];
#pragma unroll
    for (int j = 0; j < 8; j++) bias[j] = b0[c0 + j] + b1[c0 + j] + b2[c0 + j];
#pragma unroll
    for (int i = 0; i < 8; i++) {
        int r = row0 + tr * 8 + i;
        if (r >= n) continue;
        size_t off = (size_t)r * HID + c0;
#pragma unroll
        for (int g = 0; g < 2; g++) {
            float4 o;
            o.x = fmaxf(acc[i][g*4+0] + bias[g*4+0], 0.f);
            o.y = fmaxf(acc[i][g*4+1] + bias[g*4+1], 0.f);
            o.z = fmaxf(acc[i][g*4+2] + bias[g*4+2], 0.f);
            o.w = fmaxf(acc[i][g*4+3] + bias[g*4+3], 0.f);
            *(float4*)&Y[off + g * 4] = o;
        }
    }
}

// Y = relu( (X0.*rs0)@W0 + X1@W1 + bias )
__global__ __launch_bounds__(256) void gemm2_relu_k(
    const float* __restrict__ X0, const float* __restrict__ rs0, const float* __restrict__ W0,
    const float* __restrict__ X1, const float* __restrict__ W1,
    const float* __restrict__ b0,
    float* __restrict__ Y, int n)
{
    __shared__ float Xs[128][33];
    __shared__ float Ws[32][128];
    float acc[8][8];
#pragma unroll
    for (int i = 0; i < 8; i++)
#pragma unroll
        for (int j = 0; j < 8; j++) acc[i][j] = 0.0f;
    int row0 = blockIdx.x * 128;
    gemm_core_acc(X0, rs0,     W0, n, row0, Xs, Ws, acc);
    gemm_core_acc(X1, nullptr, W1, n, row0, Xs, Ws, acc);
    int tid = threadIdx.x, tr = tid >> 4, tc = tid & 15;
    int c0 = tc * 8;
#pragma unroll
    for (int i = 0; i < 8; i++) {
        int r = row0 + tr * 8 + i;
        if (r >= n) continue;
        size_t off = (size_t)r * HID + c0;
#pragma unroll
        for (int g = 0; g < 2; g++) {
            float4 o;
            o.x = fmaxf(acc[i][g*4+0] + b0[c0 + g*4+0], 0.f);
            o.y = fmaxf(acc[i][g*4+1] + b0[c0 + g*4+1], 0.f);
            o.z = fmaxf(acc[i][g*4+2] + b0[c0 + g*4+2], 0.f);
            o.w = fmaxf(acc[i][g*4+3] + b0[c0 + g*4+3], 0.f);
            *(float4*)&Y[off + g * 4] = o;
        }
    }
}

// ------------------------- classifier -----------------------------------------
__global__ __launch_bounds__(256) void classifier_k(
    const int* __restrict__ ls, const int* __restrict__ ld,
    const float* __restrict__ XS, const float* __restrict__ XM,
    float* __restrict__ out, int E)
{
    int e = (blockIdx.x * blockDim.x + threadIdx.x) >> 5;
    if (e >= E) return;
    int lane = threadIdx.x & 31;
    int s = __ldg(&ls[e]);
    int d = __ldg(&ld[e]);
    float4 a = *(const float4*)&XS[(size_t)s * HID + lane * 4];
    float4 b = *(const float4*)&XM[(size_t)d * HID + lane * 4];
    float p = a.x * b.x + a.y * b.y + a.z * b.z + a.w * b.w;
#pragma unroll
    for (int o = 16; o > 0; o >>= 1) p += __shfl_xor_sync(0xffffffffu, p, o);
    if (lane == 0) out[e] = p;
}

// ------------------------- launch ---------------------------------------------
extern "C" void kernel_launch(void* const* d_in, const int* in_sizes, int n_in,
                              void* d_out, int out_size)
{
    const int*   s2m_src   = (const int*)d_in[0];
    const int*   s2m_dst   = (const int*)d_in[1];
    const int*   m2m_src   = (const int*)d_in[2];
    const int*   m2m_dst   = (const int*)d_in[3];
    const int*   label_src = (const int*)d_in[4];
    const int*   label_dst = (const int*)d_in[5];
    const float* srna_emb  = (const float*)d_in[6];
    const float* mrna_emb  = (const float*)d_in[7];
    const float* sage_s2m_Wl = (const float*)d_in[8];
    const float* sage_s2m_bl = (const float*)d_in[9];
    const float* sage_s2m_Wr = (const float*)d_in[10];
    const float* sage_rev_Wl = (const float*)d_in[11];
    const float* sage_rev_bl = (const float*)d_in[12];
    const float* sage_rev_Wr = (const float*)d_in[13];
    const float* gcn_m2m_W   = (const float*)d_in[14];
    const float* gcn_m2m_b   = (const float*)d_in[15];
    const float* gcn_rev_W   = (const float*)d_in[16];
    const float* gcn_rev_b   = (const float*)d_in[17];
    float* out = (float*)d_out;

    float *aggm, *aggf, *aggr, *xm0, *xm1, *aggs, *xs0, *xs1;
    float *cinvm, *cinvs, *dinvf, *dinvr;
    int *cntA, *offA, *curA, *cntB, *offB, *curB;
    int *cntC, *offC, *curC, *cntD, *offD, *curD;
    int *adjA, *adjB, *adjC, *adjD;
    cudaGetSymbolAddress((void**)&aggm, g_aggm);
    cudaGetSymbolAddress((void**)&aggf, g_aggf);
    cudaGetSymbolAddress((void**)&aggr, g_aggr);
    cudaGetSymbolAddress((void**)&xm0,  g_xm0);
    cudaGetSymbolAddress((void**)&xm1,  g_xm1);
    cudaGetSymbolAddress((void**)&aggs, g_aggs);
    cudaGetSymbolAddress((void**)&xs0,  g_xs0);
    cudaGetSymbolAddress((void**)&xs1,  g_xs1);
    cudaGetSymbolAddress((void**)&cinvm, g_cinvm);
    cudaGetSymbolAddress((void**)&cinvs, g_cinvs);
    cudaGetSymbolAddress((void**)&dinvf, g_dinvf);
    cudaGetSymbolAddress((void**)&dinvr, g_dinvr);
    cudaGetSymbolAddress((void**)&cntA, g_cntA); cudaGetSymbolAddress((void**)&offA, g_offA);
    cudaGetSymbolAddress((void**)&curA, g_curA); cudaGetSymbolAddress((void**)&cntB, g_cntB);
    cudaGetSymbolAddress((void**)&offB, g_offB); cudaGetSymbolAddress((void**)&curB, g_curB);
    cudaGetSymbolAddress((void**)&cntC, g_cntC); cudaGetSymbolAddress((void**)&offC, g_offC);
    cudaGetSymbolAddress((void**)&curC, g_curC); cudaGetSymbolAddress((void**)&cntD, g_cntD);
    cudaGetSymbolAddress((void**)&offD, g_offD); cudaGetSymbolAddress((void**)&curD, g_curD);
    cudaGetSymbolAddress((void**)&adjA, g_adjA); cudaGetSymbolAddress((void**)&adjB, g_adjB);
    cudaGetSymbolAddress((void**)&adjC, g_adjC); cudaGetSymbolAddress((void**)&adjD, g_adjD);

    // ---- CSR build (per call; graph is layer-invariant) ----
    cudaMemsetAsync(cntA, 0, N_MRNA * sizeof(int));
    cudaMemsetAsync(cntB, 0, N_SRNA * sizeof(int));
    cudaMemsetAsync(cntC, 0, N_MRNA * sizeof(int));
    cudaMemsetAsync(cntD, 0, N_MRNA * sizeof(int));
    cudaMemsetAsync(curA, 0, N_MRNA * sizeof(int));
    cudaMemsetAsync(curB, 0, N_SRNA * sizeof(int));
    cudaMemsetAsync(curC, 0, N_MRNA * sizeof(int));
    cudaMemsetAsync(curD, 0, N_MRNA * sizeof(int));

    count_int_k<<<2048, 256>>>(s2m_dst, cntA, E_S2M);
    count_int_k<<<2048, 256>>>(s2m_src, cntB, E_S2M);
    count_int_k<<<2048, 256>>>(m2m_dst, cntC, E_M2M);
    count_int_k<<<2048, 256>>>(m2m_src, cntD, E_M2M);

    scan4_k<<<4, 1024>>>(cntA, offA, N_MRNA, cntB, offB, N_SRNA,
                         cntC, offC, N_MRNA, cntD, offD, N_MRNA);

    finalize_cinv_k<<<(N_MRNA + 255) / 256, 256>>>(cntA, cinvm, N_MRNA);
    finalize_cinv_k<<<(N_SRNA + 255) / 256, 256>>>(cntB, cinvs, N_SRNA);
    finalize_dinv_k<<<(N_MRNA + 255) / 256, 256>>>(cntC, dinvf, N_MRNA);
    finalize_dinv_k<<<(N_MRNA + 255) / 256, 256>>>(cntD, dinvr, N_MRNA);

    fill_k<<<2048, 256>>>(s2m_dst, s2m_src, offA, curA, adjA, E_S2M);
    fill_k<<<2048, 256>>>(s2m_src, s2m_dst, offB, curB, adjB, E_S2M);
    fill_k<<<2048, 256>>>(m2m_dst, m2m_src, offC, curC, adjC, E_M2M);
    fill_k<<<2048, 256>>>(m2m_src, m2m_dst, offD, curD, adjD, E_M2M);

    const float* xs = srna_emb;
    const float* xm = mrna_emb;
    float* xm_bufs[2] = {xm0, xm1};
    float* xs_bufs[2] = {xs0, xs1};

    const int gm = (N_MRNA + 127) / 128;
    const int gs = (N_SRNA + 127) / 128;
    const int gwm = (N_MRNA * 32 + 255) / 256;
    const int gws = (N_SRNA * 32 + 255) / 256;

    for (int l = 0; l < 2; l++) {
        const float* Wf  = gcn_m2m_W   + (size_t)l * HID * HID;
        const float* bfp = gcn_m2m_b   + (size_t)l * HID;
        const float* Wg  = gcn_rev_W   + (size_t)l * HID * HID;
        const float* brp = gcn_rev_b   + (size_t)l * HID;
        const float* sWl = sage_s2m_Wl + (size_t)l * HID * HID;
        const float* sbl = sage_s2m_bl + (size_t)l * HID;
        const float* sWr = sage_s2m_Wr + (size_t)l * HID * HID;
        const float* rWl = sage_rev_Wl + (size_t)l * HID * HID;
        const float* rbl = sage_rev_bl + (size_t)l * HID;
        const float* rWr = sage_rev_Wr + (size_t)l * HID * HID;

        // gathers (no atomics): write each destination row exactly once
        gather_k<false,false><<<gwm, 256>>>(offA, adjA, xs, nullptr, aggm, N_MRNA);
        gather_k<false,false><<<gws, 256>>>(offB, adjB, xm, nullptr, aggs, N_SRNA);
        gather_k<true, true ><<<gwm, 256>>>(offC, adjC, xm, dinvf,   aggf, N_MRNA);
        gather_k<true, true ><<<gwm, 256>>>(offD, adjD, xm, dinvr,   aggr, N_MRNA);

        // m_new = relu( (aggm.*cinvm)@sWl + xm@sWr + aggf@Wf + aggr@Wg + (sbl+bf+br) )
        gemm4_relu_k<<<gm, 256>>>(aggm, cinvm, sWl, xm, sWr, aggf, Wf, aggr, Wg,
                                  sbl, bfp, brp, xm_bufs[l], N_MRNA);
        // s_new = relu( (aggs.*cinvs)@rWl + xs@rWr + rbl )
        gemm2_relu_k<<<gs, 256>>>(aggs, cinvs, rWl, xs, rWr, rbl, xs_bufs[l], N_SRNA);

        xm = xm_bufs[l];
        xs = xs_bufs[l];
    }

    classifier_k<<<(E_LBL * 32 + 255) / 256, 256>>>(label_src, label_dst, xs, xm, out, E_LBL);
}

// round 13
// speedup vs baseline: 1.7060x; 1.0725x over previous
#include <cuda_runtime.h>
#include <cuda_bf16.h>
#include <cstdint>

#define N_SRNA 20000
#define N_MRNA 100000
#define HID    128
#define E_S2M  1000000
#define E_M2M  2000000
#define E_LBL  500000

// ------------------------- scratch (module-static) ----------------------------
__device__ float g_aggm[N_MRNA*HID];
__device__ float g_aggf[N_MRNA*HID];
__device__ float g_aggr[N_MRNA*HID];
__device__ float g_xm0 [N_MRNA*HID];
__device__ float g_xm1 [N_MRNA*HID];
__device__ float g_aggs[N_SRNA*HID];
__device__ float g_xs0 [N_SRNA*HID];
__device__ float g_xs1 [N_SRNA*HID];

__device__ float g_cinvm[N_MRNA];
__device__ float g_cinvs[N_SRNA];
__device__ float g_dinvf[N_MRNA];
__device__ float g_dinvr[N_MRNA];

// bf16-split weights, ORIGINAL [k][n] layout: 12 mats (2 layers x [sWl,sWr,Wf,Wg,rWl,rWr])
__device__ __nv_bfloat16 g_wt_hi[12*16384];
__device__ __nv_bfloat16 g_wt_lo[12*16384];
__device__ float g_bias_m[2*128];
__device__ float g_bias_s[2*128];

// CSR structures
__device__ int g_cntA[N_MRNA];  __device__ int g_offA[N_MRNA+1];  __device__ int g_curA[N_MRNA];
__device__ int g_cntB[N_SRNA];  __device__ int g_offB[N_SRNA+1];  __device__ int g_curB[N_SRNA];
__device__ int g_cntC[N_MRNA];  __device__ int g_offC[N_MRNA+1];  __device__ int g_curC[N_MRNA];
__device__ int g_cntD[N_MRNA];  __device__ int g_offD[N_MRNA+1];  __device__ int g_curD[N_MRNA];
__device__ int g_adjA[E_S2M];
__device__ int g_adjB[E_S2M];
__device__ int g_adjC[E_M2M];
__device__ int g_adjD[E_M2M];

// ------------------------- helpers --------------------------------------------
__device__ __forceinline__ uint32_t smem_u32(const void* p) {
    uint32_t a;
    asm("{ .reg .u64 t; cvta.to.shared.u64 t, %1; cvt.u32.u64 %0, t; }" : "=r"(a) : "l"(p));
    return a;
}
__device__ __forceinline__ void ldsm_x4(uint32_t* r, uint32_t addr) {
    asm volatile("ldmatrix.sync.aligned.m8n8.x4.shared.b16 {%0,%1,%2,%3}, [%4];"
        : "=r"(r[0]), "=r"(r[1]), "=r"(r[2]), "=r"(r[3]) : "r"(addr));
}
__device__ __forceinline__ void ldsm_x4_t(uint32_t* r, uint32_t addr) {
    asm volatile("ldmatrix.sync.aligned.m8n8.x4.trans.shared.b16 {%0,%1,%2,%3}, [%4];"
        : "=r"(r[0]), "=r"(r[1]), "=r"(r[2]), "=r"(r[3]) : "r"(addr));
}
__device__ __forceinline__ void mma16816(float* c, const uint32_t* a, const uint32_t* b) {
    asm volatile(
        "mma.sync.aligned.m16n8k16.row.col.f32.bf16.bf16.f32 "
        "{%0,%1,%2,%3}, {%4,%5,%6,%7}, {%8,%9}, {%0,%1,%2,%3};"
        : "+f"(c[0]), "+f"(c[1]), "+f"(c[2]), "+f"(c[3])
        : "r"(a[0]), "r"(a[1]), "r"(a[2]), "r"(a[3]), "r"(b[0]), "r"(b[1]));
}

// ------------------------- counting / scan / fill ------------------------------
__global__ void count_int_k(const int* __restrict__ idx, int* __restrict__ cnt, int E) {
    int i = blockIdx.x * blockDim.x + threadIdx.x;
    int stride = gridDim.x * blockDim.x;
    for (; i < E; i += stride) atomicAdd(&cnt[idx[i]], 1);
}
__global__ void finalize_cinv_k(const int* __restrict__ cnt, float* __restrict__ o, int n) {
    int i = blockIdx.x * blockDim.x + threadIdx.x;
    if (i < n) o[i] = 1.0f / fmaxf((float)cnt[i], 1.0f);
}
__global__ void finalize_dinv_k(const int* __restrict__ cnt, float* __restrict__ o, int n) {
    int i = blockIdx.x * blockDim.x + threadIdx.x;
    if (i < n) o[i] = rsqrtf((float)cnt[i] + 1.0f);
}

__device__ void scan_body(const int* __restrict__ cnt, int* __restrict__ off, int n) {
    __shared__ int wsum[32];
    __shared__ int s_carry;
    int tid = threadIdx.x, lane = tid & 31, wid = tid >> 5;
    if (tid == 0) { s_carry = 0; off[0] = 0; }
    __syncthreads();
    for (int base = 0; base < n; base += 4096) {
        int i0 = base + tid * 4;
        int v0 = (i0 + 0 < n) ? cnt[i0 + 0] : 0;
        int v1 = (i0 + 1 < n) ? cnt[i0 + 1] : 0;
        int v2 = (i0 + 2 < n) ? cnt[i0 + 2] : 0;
        int v3 = (i0 + 3 < n) ? cnt[i0 + 3] : 0;
        int t = v0 + v1 + v2 + v3;
        int x = t;
#pragma unroll
        for (int d = 1; d < 32; d <<= 1) {
            int y = __shfl_up_sync(0xffffffffu, x, d);
            if (lane >= d) x += y;
        }
        if (lane == 31) wsum[wid] = x;
        __syncthreads();
        if (wid == 0) {
            int z = wsum[lane];
#pragma unroll
            for (int d = 1; d < 32; d <<= 1) {
                int y = __shfl_up_sync(0xffffffffu, z, d);
                if (lane >= d) z += y;
            }
            wsum[lane] = z;
        }
        __syncthreads();
        int warpoff = (wid == 0) ? 0 : wsum[wid - 1];
        int excl = warpoff + (x - t) + s_carry;
        if (i0 + 0 < n) off[i0 + 1] = excl + v0;
        if (i0 + 1 < n) off[i0 + 2] = excl + v0 + v1;
        if (i0 + 2 < n) off[i0 + 3] = excl + v0 + v1 + v2;
        if (i0 + 3 < n) off[i0 + 4] = excl + v0 + v1 + v2 + v3;
        __syncthreads();
        if (tid == 0) s_carry += wsum[31];
        __syncthreads();
    }
}
__global__ __launch_bounds__(1024) void scan4_k(
    const int* c0, int* o0, int n0, const int* c1, int* o1, int n1,
    const int* c2, int* o2, int n2, const int* c3, int* o3, int n3)
{
    switch (blockIdx.x) {
        case 0: scan_body(c0, o0, n0); break;
        case 1: scan_body(c1, o1, n1); break;
        case 2: scan_body(c2, o2, n2); break;
        default: scan_body(c3, o3, n3); break;
    }
}
__global__ void fill_k(const int* __restrict__ key, const int* __restrict__ val,
                       const int* __restrict__ off, int* __restrict__ cur,
                       int* __restrict__ adj, int E)
{
    int i = blockIdx.x * blockDim.x + threadIdx.x;
    int stride = gridDim.x * blockDim.x;
    for (; i < E; i += stride) {
        int k = key[i];
        int pos = off[k] + atomicAdd(&cur[k], 1);
        adj[pos] = val[i];
    }
}

// ------------------------- warp-per-node gather --------------------------------
template<bool WEIGHTED, bool SELF>
__global__ __launch_bounds__(256) void gather_k(
    const int* __restrict__ off, const int* __restrict__ adj,
    const float* __restrict__ X, const float* __restrict__ dinv,
    float* __restrict__ OUT, int n)
{
    int node = (blockIdx.x * blockDim.x + threadIdx.x) >> 5;
    if (node >= n) return;
    int lane = threadIdx.x & 31;
    int beg = off[node], end = off[node + 1];

    float4 selfv = make_float4(0.f, 0.f, 0.f, 0.f);
    float dd = 0.f;
    if (SELF) {
        dd = __ldg(&dinv[node]);
        selfv = *(const float4*)&X[(size_t)node * HID + lane * 4];
    }

    float4 acc = make_float4(0.f, 0.f, 0.f, 0.f);
    for (int base = beg; base < end; base += 32) {
        int m = end - base;
        int nb = 0; float w = 0.f;
        if (lane < m) {
            nb = __ldg(&adj[base + lane]);
            if (WEIGHTED) w = __ldg(&dinv[nb]);
        }
        int iters = m < 32 ? m : 32;
#pragma unroll 8
        for (int j = 0; j < iters; j++) {
            int id = __shfl_sync(0xffffffffu, nb, j);
            float wj = WEIGHTED ? __shfl_sync(0xffffffffu, w, j) : 1.0f;
            float4 v = *(const float4*)&X[(size_t)id * HID + lane * 4];
            acc.x = fmaf(wj, v.x, acc.x);
            acc.y = fmaf(wj, v.y, acc.y);
            acc.z = fmaf(wj, v.z, acc.z);
            acc.w = fmaf(wj, v.w, acc.w);
        }
    }
    if (SELF) {
        acc.x = dd * (acc.x + dd * selfv.x);
        acc.y = dd * (acc.y + dd * selfv.y);
        acc.z = dd * (acc.z + dd * selfv.z);
        acc.w = dd * (acc.w + dd * selfv.w);
    }
    *(float4*)&OUT[(size_t)node * HID + lane * 4] = acc;
}

// ------------------------- weight bf16 split (keep [k][n] layout) --------------
__global__ void tsplit_k(const float* __restrict__ sWl, const float* __restrict__ sWr,
                         const float* __restrict__ Wf,  const float* __restrict__ Wg,
                         const float* __restrict__ rWl, const float* __restrict__ rWr,
                         __nv_bfloat16* __restrict__ oh, __nv_bfloat16* __restrict__ ol)
{
    int gid = blockIdx.x * blockDim.x + threadIdx.x;
    if (gid >= 12 * 16384) return;
    int mat = gid >> 14;
    int e = gid & 16383;
    int l = mat / 6, m6 = mat % 6;
    const float* W;
    switch (m6) {
        case 0: W = sWl; break; case 1: W = sWr; break; case 2: W = Wf; break;
        case 3: W = Wg;  break; case 4: W = rWl; break; default: W = rWr; break;
    }
    W += l * 16384;
    float v = W[e];
    __nv_bfloat16 h = __float2bfloat16(v);
    oh[gid] = h;
    ol[gid] = __float2bfloat16(v - __bfloat162float(h));
}

__global__ void bias_k(const float* __restrict__ sbl, const float* __restrict__ bf,
                       const float* __restrict__ br,  const float* __restrict__ rbl,
                       float* __restrict__ bm, float* __restrict__ bs)
{
    int i = threadIdx.x;   // 0..255 -> 2 layers x 128 cols
    bm[i] = sbl[i] + bf[i] + br[i];
    bs[i] = rbl[i];
}

// ------------------------- mma.sync bf16-split GEMM ----------------------------
// Y[128 x 128 tile] = relu( sum_s (X_s .* rs?) @ W_s + bias )
// hi/lo split: ah*bh + al*bh + ah*bl (fp32 accumulate).
#define A_STRIDE 40   // halfs per row (32 + 8 pad); 80B, 16B-aligned
#define B_STRIDE 136  // halfs per row (128 + 8 pad); 272B

template<int NSRC>
__global__ __launch_bounds__(256) void gemm_mma_k(
    const float* __restrict__ X0, const float* __restrict__ X1,
    const float* __restrict__ X2, const float* __restrict__ X3,
    const float* __restrict__ rs0,
    const __nv_bfloat16* __restrict__ Wh, const __nv_bfloat16* __restrict__ Wl,
    const float* __restrict__ bias, float* __restrict__ Y, int n)
{
    __shared__ __nv_bfloat16 sAh[128][A_STRIDE];
    __shared__ __nv_bfloat16 sAl[128][A_STRIDE];
    __shared__ __nv_bfloat16 sBh[32][B_STRIDE];
    __shared__ __nv_bfloat16 sBl[32][B_STRIDE];

    int tid = threadIdx.x, wid = tid >> 5, lane = tid & 31;
    int row0 = blockIdx.x * 128;
    int wm = (wid >> 2) * 64;     // warp m offset: 0 or 64
    int wn = (wid & 3) * 32;      // warp n offset: 0,32,64,96

    const float* Xs_[4] = {X0, X1, X2, X3};

    float acc[4][4][4];
#pragma unroll
    for (int i = 0; i < 4; i++)
#pragma unroll
        for (int j = 0; j < 4; j++)
#pragma unroll
            for (int q = 0; q < 4; q++) acc[i][j][q] = 0.0f;

    uint32_t aHiB = smem_u32(&sAh[0][0]);
    uint32_t aLoB = smem_u32(&sAl[0][0]);
    uint32_t bHiB = smem_u32(&sBh[0][0]);
    uint32_t bLoB = smem_u32(&sBl[0][0]);

    const int NCH = NSRC * 4;
    for (int ks = 0; ks < NCH; ks++) {
        int s = ks >> 2, kb = ks & 3;
        const float* Xp = Xs_[s];
        const __nv_bfloat16* whp = Wh + s * 16384;
        const __nv_bfloat16* wlp = Wl + s * 16384;
        __syncthreads();
        // stage A: 128 rows x 32 k, fp32 -> bf16 hi/lo
#pragma unroll
        for (int u = 0; u < 4; u++) {
            int slot = tid + u * 256;          // 0..1023
            int r = slot >> 3, c4 = (slot & 7) * 4;
            int gr = row0 + r;
            float4 v = make_float4(0.f, 0.f, 0.f, 0.f);
            if (gr < n) {
                v = *(const float4*)&Xp[(size_t)gr * HID + kb * 32 + c4];
                if (s == 0) { float t = rs0[gr]; v.x *= t; v.y *= t; v.z *= t; v.w *= t; }
            }
            __nv_bfloat16 hx = __float2bfloat16(v.x), hy = __float2bfloat16(v.y);
            __nv_bfloat16 hz = __float2bfloat16(v.z), hw = __float2bfloat16(v.w);
            __nv_bfloat162 h01; h01.x = hx; h01.y = hy;
            __nv_bfloat162 h23; h23.x = hz; h23.y = hw;
            __nv_bfloat162 l01, l23;
            l01.x = __float2bfloat16(v.x - __bfloat162float(hx));
            l01.y = __float2bfloat16(v.y - __bfloat162float(hy));
            l23.x = __float2bfloat16(v.z - __bfloat162float(hz));
            l23.y = __float2bfloat16(v.w - __bfloat162float(hw));
            *(__nv_bfloat162*)&sAh[r][c4]     = h01;
            *(__nv_bfloat162*)&sAh[r][c4 + 2] = h23;
            *(__nv_bfloat162*)&sAl[r][c4]     = l01;
            *(__nv_bfloat162*)&sAl[r][c4 + 2] = l23;
        }
        // stage B: 32 k-rows x 128 n, already bf16 (16B vector copies)
#pragma unroll
        for (int u = 0; u < 2; u++) {
            int slot = tid + u * 256;          // 0..511
            int r = slot >> 4, c8 = (slot & 15) * 8;
            int go = (kb * 32 + r) * 128 + c8;
            *(uint4*)&sBh[r][c8] = *(const uint4*)&whp[go];
            *(uint4*)&sBl[r][c8] = *(const uint4*)&wlp[go];
        }
        __syncthreads();

#pragma unroll
        for (int kk = 0; kk < 32; kk += 16) {
            uint32_t ah[4][4], al[4][4], bh[4][2], bl[4][2];
            int arow = (lane & 15), acolh = kk + (lane >> 4) * 8;
#pragma unroll
            for (int mi = 0; mi < 4; mi++) {
                uint32_t off = ((wm + mi * 16 + arow) * A_STRIDE + acolh) * 2;
                ldsm_x4(ah[mi], aHiB + off);
                ldsm_x4(al[mi], aLoB + off);
            }
            int brow = kk + (lane & 15);
#pragma unroll
            for (int ni = 0; ni < 2; ni++) {
                uint32_t off = (brow * B_STRIDE + wn + ni * 16 + (lane >> 4) * 8) * 2;
                uint32_t t[4];
                ldsm_x4_t(t, bHiB + off);
                bh[2 * ni][0] = t[0]; bh[2 * ni][1] = t[1];
                bh[2 * ni + 1][0] = t[2]; bh[2 * ni + 1][1] = t[3];
                ldsm_x4_t(t, bLoB + off);
                bl[2 * ni][0] = t[0]; bl[2 * ni][1] = t[1];
                bl[2 * ni + 1][0] = t[2]; bl[2 * ni + 1][1] = t[3];
            }
#pragma unroll
            for (int mi = 0; mi < 4; mi++)
#pragma unroll
                for (int nj = 0; nj < 4; nj++) {
                    mma16816(acc[mi][nj], ah[mi], bh[nj]);
                    mma16816(acc[mi][nj], al[mi], bh[nj]);
                    mma16816(acc[mi][nj], ah[mi], bl[nj]);
                }
        }
    }

    // epilogue: bias + relu, float2 stores
    int gid = lane >> 2, tig = lane & 3;
#pragma unroll
    for (int mi = 0; mi < 4; mi++) {
        int r0 = row0 + wm + mi * 16 + gid;
        int r1 = r0 + 8;
#pragma unroll
        for (int nj = 0; nj < 4; nj++) {
            int c = wn + nj * 8 + tig * 2;
            float b0 = __ldg(&bias[c]), b1 = __ldg(&bias[c + 1]);
            if (r0 < n) {
                float2 o;
                o.x = fmaxf(acc[mi][nj][0] + b0, 0.f);
                o.y = fmaxf(acc[mi][nj][1] + b1, 0.f);
                *(float2*)&Y[(size_t)r0 * HID + c] = o;
            }
            if (r1 < n) {
                float2 o;
                o.x = fmaxf(acc[mi][nj][2] + b0, 0.f);
                o.y = fmaxf(acc[mi][nj][3] + b1, 0.f);
                *(float2*)&Y[(size_t)r1 * HID + c] = o;
            }
        }
    }
}

// ------------------------- classifier -----------------------------------------
__global__ __launch_bounds__(256) void classifier_k(
    const int* __restrict__ ls, const int* __restrict__ ld,
    const float* __restrict__ XS, const float* __restrict__ XM,
    float* __restrict__ out, int E)
{
    int e = (blockIdx.x * blockDim.x + threadIdx.x) >> 5;
    if (e >= E) return;
    int lane = threadIdx.x & 31;
    int s = __ldg(&ls[e]);
    int d = __ldg(&ld[e]);
    float4 a = *(const float4*)&XS[(size_t)s * HID + lane * 4];
    float4 b = *(const float4*)&XM[(size_t)d * HID + lane * 4];
    float p = a.x * b.x + a.y * b.y + a.z * b.z + a.w * b.w;
#pragma unroll
    for (int o = 16; o > 0; o >>= 1) p += __shfl_xor_sync(0xffffffffu, p, o);
    if (lane == 0) out[e] = p;
}

// ------------------------- launch ---------------------------------------------
extern "C" void kernel_launch(void* const* d_in, const int* in_sizes, int n_in,
                              void* d_out, int out_size)
{
    const int*   s2m_src   = (const int*)d_in[0];
    const int*   s2m_dst   = (const int*)d_in[1];
    const int*   m2m_src   = (const int*)d_in[2];
    const int*   m2m_dst   = (const int*)d_in[3];
    const int*   label_src = (const int*)d_in[4];
    const int*   label_dst = (const int*)d_in[5];
    const float* srna_emb  = (const float*)d_in[6];
    const float* mrna_emb  = (const float*)d_in[7];
    const float* sage_s2m_Wl = (const float*)d_in[8];
    const float* sage_s2m_bl = (const float*)d_in[9];
    const float* sage_s2m_Wr = (const float*)d_in[10];
    const float* sage_rev_Wl = (const float*)d_in[11];
    const float* sage_rev_bl = (const float*)d_in[12];
    const float* sage_rev_Wr = (const float*)d_in[13];
    const float* gcn_m2m_W   = (const float*)d_in[14];
    const float* gcn_m2m_b   = (const float*)d_in[15];
    const float* gcn_rev_W   = (const float*)d_in[16];
    const float* gcn_rev_b   = (const float*)d_in[17];
    float* out = (float*)d_out;

    float *aggm, *aggf, *aggr, *xm0, *xm1, *aggs, *xs0, *xs1;
    float *cinvm, *cinvs, *dinvf, *dinvr, *bm, *bs;
    __nv_bfloat16 *wth, *wtl;
    int *cntA, *offA, *curA, *cntB, *offB, *curB;
    int *cntC, *offC, *curC, *cntD, *offD, *curD;
    int *adjA, *adjB, *adjC, *adjD;
    cudaGetSymbolAddress((void**)&aggm, g_aggm);
    cudaGetSymbolAddress((void**)&aggf, g_aggf);
    cudaGetSymbolAddress((void**)&aggr, g_aggr);
    cudaGetSymbolAddress((void**)&xm0,  g_xm0);
    cudaGetSymbolAddress((void**)&xm1,  g_xm1);
    cudaGetSymbolAddress((void**)&aggs, g_aggs);
    cudaGetSymbolAddress((void**)&xs0,  g_xs0);
    cudaGetSymbolAddress((void**)&xs1,  g_xs1);
    cudaGetSymbolAddress((void**)&cinvm, g_cinvm);
    cudaGetSymbolAddress((void**)&cinvs, g_cinvs);
    cudaGetSymbolAddress((void**)&dinvf, g_dinvf);
    cudaGetSymbolAddress((void**)&dinvr, g_dinvr);
    cudaGetSymbolAddress((void**)&wth, g_wt_hi);
    cudaGetSymbolAddress((void**)&wtl, g_wt_lo);
    cudaGetSymbolAddress((void**)&bm,  g_bias_m);
    cudaGetSymbolAddress((void**)&bs,  g_bias_s);
    cudaGetSymbolAddress((void**)&cntA, g_cntA); cudaGetSymbolAddress((void**)&offA, g_offA);
    cudaGetSymbolAddress((void**)&curA, g_curA); cudaGetSymbolAddress((void**)&cntB, g_cntB);
    cudaGetSymbolAddress((void**)&offB, g_offB); cudaGetSymbolAddress((void**)&curB, g_curB);
    cudaGetSymbolAddress((void**)&cntC, g_cntC); cudaGetSymbolAddress((void**)&offC, g_offC);
    cudaGetSymbolAddress((void**)&curC, g_curC); cudaGetSymbolAddress((void**)&cntD, g_cntD);
    cudaGetSymbolAddress((void**)&offD, g_offD); cudaGetSymbolAddress((void**)&curD, g_curD);
    cudaGetSymbolAddress((void**)&adjA, g_adjA); cudaGetSymbolAddress((void**)&adjB, g_adjB);
    cudaGetSymbolAddress((void**)&adjC, g_adjC); cudaGetSymbolAddress((void**)&adjD, g_adjD);

    // ---- weight prep (bf16 split) + biases ----
    tsplit_k<<<(12 * 16384 + 255) / 256, 256>>>(sage_s2m_Wl, sage_s2m_Wr, gcn_m2m_W,
                                                gcn_rev_W, sage_rev_Wl, sage_rev_Wr, wth, wtl);
    bias_k<<<1, 256>>>(sage_s2m_bl, gcn_m2m_b, gcn_rev_b, sage_rev_bl, bm, bs);

    // ---- CSR build ----
    cudaMemsetAsync(cntA, 0, N_MRNA * sizeof(int));
    cudaMemsetAsync(cntB, 0, N_SRNA * sizeof(int));
    cudaMemsetAsync(cntC, 0, N_MRNA * sizeof(int));
    cudaMemsetAsync(cntD, 0, N_MRNA * sizeof(int));
    cudaMemsetAsync(curA, 0, N_MRNA * sizeof(int));
    cudaMemsetAsync(curB, 0, N_SRNA * sizeof(int));
    cudaMemsetAsync(curC, 0, N_MRNA * sizeof(int));
    cudaMemsetAsync(curD, 0, N_MRNA * sizeof(int));

    count_int_k<<<2048, 256>>>(s2m_dst, cntA, E_S2M);
    count_int_k<<<2048, 256>>>(s2m_src, cntB, E_S2M);
    count_int_k<<<2048, 256>>>(m2m_dst, cntC, E_M2M);
    count_int_k<<<2048, 256>>>(m2m_src, cntD, E_M2M);

    scan4_k<<<4, 1024>>>(cntA, offA, N_MRNA, cntB, offB, N_SRNA,
                         cntC, offC, N_MRNA, cntD, offD, N_MRNA);

    finalize_cinv_k<<<(N_MRNA + 255) / 256, 256>>>(cntA, cinvm, N_MRNA);
    finalize_cinv_k<<<(N_SRNA + 255) / 256, 256>>>(cntB, cinvs, N_SRNA);
    finalize_dinv_k<<<(N_MRNA + 255) / 256, 256>>>(cntC, dinvf, N_MRNA);
    finalize_dinv_k<<<(N_MRNA + 255) / 256, 256>>>(cntD, dinvr, N_MRNA);

    fill_k<<<2048, 256>>>(s2m_dst, s2m_src, offA, curA, adjA, E_S2M);
    fill_k<<<2048, 256>>>(s2m_src, s2m_dst, offB, curB, adjB, E_S2M);
    fill_k<<<2048, 256>>>(m2m_dst, m2m_src, offC, curC, adjC, E_M2M);
    fill_k<<<2048, 256>>>(m2m_src, m2m_dst, offD, curD, adjD, E_M2M);

    const float* xs = srna_emb;
    const float* xm = mrna_emb;
    float* xm_bufs[2] = {xm0, xm1};
    float* xs_bufs[2] = {xs0, xs1};

    const int gm = (N_MRNA + 127) / 128;
    const int gs = (N_SRNA + 127) / 128;
    const int gwm = (N_MRNA * 32 + 255) / 256;
    const int gws = (N_SRNA * 32 + 255) / 256;

    for (int l = 0; l < 2; l++) {
        const __nv_bfloat16* wth_m = wth + (size_t)(l * 6 + 0) * 16384;
        const __nv_bfloat16* wtl_m = wtl + (size_t)(l * 6 + 0) * 16384;
        const __nv_bfloat16* wth_s = wth + (size_t)(l * 6 + 4) * 16384;
        const __nv_bfloat16* wtl_s = wtl + (size_t)(l * 6 + 4) * 16384;

        gather_k<false,false><<<gwm, 256>>>(offA, adjA, xs, nullptr, aggm, N_MRNA);
        gather_k<false,false><<<gws, 256>>>(offB, adjB, xm, nullptr, aggs, N_SRNA);
        gather_k<true, true ><<<gwm, 256>>>(offC, adjC, xm, dinvf,   aggf, N_MRNA);
        gather_k<true, true ><<<gwm, 256>>>(offD, adjD, xm, dinvr,   aggr, N_MRNA);

        // m_new = relu( (aggm.*cinvm)@sWl + xm@sWr + aggf@Wf + aggr@Wg + bias_m )
        gemm_mma_k<4><<<gm, 256>>>(aggm, xm, aggf, aggr, cinvm,
                                   wth_m, wtl_m, bm + l * 128, xm_bufs[l], N_MRNA);
        // s_new = relu( (aggs.*cinvs)@rWl + xs@rWr + bias_s )
        gemm_mma_k<2><<<gs, 256>>>(aggs, xs, nullptr, nullptr, cinvs,
                                   wth_s, wtl_s, bs + l * 128, xs_bufs[l], N_SRNA);

        xm = xm_bufs[l];
        xs = xs_bufs[l];
    }

    classifier_k<<<(E_LBL * 32 + 255) / 256, 256>>>(label_src, label_dst, xs, xm, out, E_LBL);
}

// round 14
// speedup vs baseline: 1.7993x; 1.0547x over previous
#include <cuda_runtime.h>
#include <cuda_bf16.h>
#include <cstdint>

#define N_SRNA 20000
#define N_MRNA 100000
#define HID    128
#define E_S2M  1000000
#define E_M2M  2000000
#define E_LBL  500000

#define CNT_TOT (3*N_MRNA + N_SRNA)
// cnt/cur layout: A [0,N_MRNA), C [N_MRNA,2N), D [2N,3N), B [3N, 3N+N_SRNA)
#define O_A 0
#define O_C N_MRNA
#define O_D (2*N_MRNA)
#define O_B (3*N_MRNA)
// off layout (each needs n+1)
#define F_A 0
#define F_C (N_MRNA+1)
#define F_D (2*(N_MRNA+1))
#define F_B (3*(N_MRNA+1))
#define OFF_TOT (3*(N_MRNA+1) + (N_SRNA+1))

// ------------------------- scratch (module-static) ----------------------------
__device__ float g_aggm[N_MRNA*HID];
__device__ float g_aggf[N_MRNA*HID];
__device__ float g_aggr[N_MRNA*HID];
__device__ float g_xm0 [N_MRNA*HID];
__device__ float g_xm1 [N_MRNA*HID];
__device__ float g_aggs[N_SRNA*HID];
__device__ float g_xs0 [N_SRNA*HID];
__device__ float g_xs1 [N_SRNA*HID];

__device__ float g_cinvm[N_MRNA];
__device__ float g_cinvs[N_SRNA];
__device__ float g_dinvf[N_MRNA];
__device__ float g_dinvr[N_MRNA];

__device__ __nv_bfloat16 g_wt_hi[12*16384];
__device__ __nv_bfloat16 g_wt_lo[12*16384];
__device__ float g_bias_m[2*128];
__device__ float g_bias_s[2*128];

__device__ int g_cnt[CNT_TOT];
__device__ int g_cur[CNT_TOT];
__device__ int g_off[OFF_TOT];
__device__ int g_adjA[E_S2M];
__device__ int g_adjB[E_S2M];
__device__ int g_adjC[E_M2M];
__device__ int g_adjD[E_M2M];

// ------------------------- helpers --------------------------------------------
__device__ __forceinline__ uint32_t smem_u32(const void* p) {
    uint32_t a;
    asm("{ .reg .u64 t; cvta.to.shared.u64 t, %1; cvt.u32.u64 %0, t; }" : "=r"(a) : "l"(p));
    return a;
}
__device__ __forceinline__ void ldsm_x4(uint32_t* r, uint32_t addr) {
    asm volatile("ldmatrix.sync.aligned.m8n8.x4.shared.b16 {%0,%1,%2,%3}, [%4];"
        : "=r"(r[0]), "=r"(r[1]), "=r"(r[2]), "=r"(r[3]) : "r"(addr));
}
__device__ __forceinline__ void ldsm_x4_t(uint32_t* r, uint32_t addr) {
    asm volatile("ldmatrix.sync.aligned.m8n8.x4.trans.shared.b16 {%0,%1,%2,%3}, [%4];"
        : "=r"(r[0]), "=r"(r[1]), "=r"(r[2]), "=r"(r[3]) : "r"(addr));
}
__device__ __forceinline__ void mma16816(float* c, const uint32_t* a, const uint32_t* b) {
    asm volatile(
        "mma.sync.aligned.m16n8k16.row.col.f32.bf16.bf16.f32 "
        "{%0,%1,%2,%3}, {%4,%5,%6,%7}, {%8,%9}, {%0,%1,%2,%3};"
        : "+f"(c[0]), "+f"(c[1]), "+f"(c[2]), "+f"(c[3])
        : "r"(a[0]), "r"(a[1]), "r"(a[2]), "r"(a[3]), "r"(b[0]), "r"(b[1]));
}

// ------------------------- fused count / fill / finalize -----------------------
#define E_TOT (2*E_S2M + 2*E_M2M)

__global__ void count_all_k(const int* __restrict__ s2m_src, const int* __restrict__ s2m_dst,
                            const int* __restrict__ m2m_src, const int* __restrict__ m2m_dst,
                            int* __restrict__ cnt)
{
    int i = blockIdx.x * blockDim.x + threadIdx.x;
    int stride = gridDim.x * blockDim.x;
    for (; i < E_TOT; i += stride) {
        if (i < E_S2M)                    atomicAdd(&cnt[O_A + s2m_dst[i]], 1);
        else if (i < 2*E_S2M)             atomicAdd(&cnt[O_B + s2m_src[i - E_S2M]], 1);
        else if (i < 2*E_S2M + E_M2M)     atomicAdd(&cnt[O_C + m2m_dst[i - 2*E_S2M]], 1);
        else                              atomicAdd(&cnt[O_D + m2m_src[i - 2*E_S2M - E_M2M]], 1);
    }
}

__global__ void fill_all_k(const int* __restrict__ s2m_src, const int* __restrict__ s2m_dst,
                           const int* __restrict__ m2m_src, const int* __restrict__ m2m_dst,
                           const int* __restrict__ off, int* __restrict__ cur,
                           int* __restrict__ adjA, int* __restrict__ adjB,
                           int* __restrict__ adjC, int* __restrict__ adjD)
{
    int i = blockIdx.x * blockDim.x + threadIdx.x;
    int stride = gridDim.x * blockDim.x;
    for (; i < E_TOT; i += stride) {
        if (i < E_S2M) {
            int k = s2m_dst[i];
            int pos = off[F_A + k] + atomicAdd(&cur[O_A + k], 1);
            adjA[pos] = s2m_src[i];
        } else if (i < 2*E_S2M) {
            int j = i - E_S2M;
            int k = s2m_src[j];
            int pos = off[F_B + k] + atomicAdd(&cur[O_B + k], 1);
            adjB[pos] = s2m_dst[j];
        } else if (i < 2*E_S2M + E_M2M) {
            int j = i - 2*E_S2M;
            int k = m2m_dst[j];
            int pos = off[F_C + k] + atomicAdd(&cur[O_C + k], 1);
            adjC[pos] = m2m_src[j];
        } else {
            int j = i - 2*E_S2M - E_M2M;
            int k = m2m_src[j];
            int pos = off[F_D + k] + atomicAdd(&cur[O_D + k], 1);
            adjD[pos] = m2m_dst[j];
        }
    }
}

__global__ void finalize_all_k(const int* __restrict__ cnt,
                               float* __restrict__ cinvm, float* __restrict__ cinvs,
                               float* __restrict__ dinvf, float* __restrict__ dinvr)
{
    int i = blockIdx.x * blockDim.x + threadIdx.x;
    if (i < N_MRNA) {
        cinvm[i] = 1.0f / fmaxf((float)cnt[O_A + i], 1.0f);
        dinvf[i] = rsqrtf((float)cnt[O_C + i] + 1.0f);
        dinvr[i] = rsqrtf((float)cnt[O_D + i] + 1.0f);
    }
    if (i < N_SRNA) {
        cinvs[i] = 1.0f / fmaxf((float)cnt[O_B + i], 1.0f);
    }
}

// ------------------------- 4-way exclusive scan --------------------------------
__device__ void scan_body(const int* __restrict__ cnt, int* __restrict__ off, int n) {
    __shared__ int wsum[32];
    __shared__ int s_carry;
    int tid = threadIdx.x, lane = tid & 31, wid = tid >> 5;
    if (tid == 0) { s_carry = 0; off[0] = 0; }
    __syncthreads();
    for (int base = 0; base < n; base += 4096) {
        int i0 = base + tid * 4;
        int v0 = (i0 + 0 < n) ? cnt[i0 + 0] : 0;
        int v1 = (i0 + 1 < n) ? cnt[i0 + 1] : 0;
        int v2 = (i0 + 2 < n) ? cnt[i0 + 2] : 0;
        int v3 = (i0 + 3 < n) ? cnt[i0 + 3] : 0;
        int t = v0 + v1 + v2 + v3;
        int x = t;
#pragma unroll
        for (int d = 1; d < 32; d <<= 1) {
            int y = __shfl_up_sync(0xffffffffu, x, d);
            if (lane >= d) x += y;
        }
        if (lane == 31) wsum[wid] = x;
        __syncthreads();
        if (wid == 0) {
            int z = wsum[lane];
#pragma unroll
            for (int d = 1; d < 32; d <<= 1) {
                int y = __shfl_up_sync(0xffffffffu, z, d);
                if (lane >= d) z += y;
            }
            wsum[lane] = z;
        }
        __syncthreads();
        int warpoff = (wid == 0) ? 0 : wsum[wid - 1];
        int excl = warpoff + (x - t) + s_carry;
        if (i0 + 0 < n) off[i0 + 1] = excl + v0;
        if (i0 + 1 < n) off[i0 + 2] = excl + v0 + v1;
        if (i0 + 2 < n) off[i0 + 3] = excl + v0 + v1 + v2;
        if (i0 + 3 < n) off[i0 + 4] = excl + v0 + v1 + v2 + v3;
        __syncthreads();
        if (tid == 0) s_carry += wsum[31];
        __syncthreads();
    }
}
__global__ __launch_bounds__(1024) void scan4_k(const int* cnt, int* off) {
    switch (blockIdx.x) {
        case 0: scan_body(cnt + O_A, off + F_A, N_MRNA); break;
        case 1: scan_body(cnt + O_B, off + F_B, N_SRNA); break;
        case 2: scan_body(cnt + O_C, off + F_C, N_MRNA); break;
        default: scan_body(cnt + O_D, off + F_D, N_MRNA); break;
    }
}

// ------------------------- fused gather (4 jobs, 1 launch) ---------------------
struct GathJob {
    const int* off; const int* adj; const float* X; const float* dinv;
    float* OUT; int n; int block0;
};

__global__ __launch_bounds__(256) void gather_all_k(GathJob j0, GathJob j1,
                                                    GathJob j2, GathJob j3)
{
    int b = blockIdx.x;
    const int* off; const int* adj; const float* X; const float* dinv;
    float* OUT; int n; int lb; bool wt;
    if (b >= j3.block0)      { off=j3.off; adj=j3.adj; X=j3.X; dinv=j3.dinv; OUT=j3.OUT; n=j3.n; lb=b-j3.block0; wt=true; }
    else if (b >= j2.block0) { off=j2.off; adj=j2.adj; X=j2.X; dinv=j2.dinv; OUT=j2.OUT; n=j2.n; lb=b-j2.block0; wt=true; }
    else if (b >= j1.block0) { off=j1.off; adj=j1.adj; X=j1.X; dinv=j1.dinv; OUT=j1.OUT; n=j1.n; lb=b-j1.block0; wt=false; }
    else                     { off=j0.off; adj=j0.adj; X=j0.X; dinv=j0.dinv; OUT=j0.OUT; n=j0.n; lb=b-j0.block0; wt=false; }

    int node = (lb * 256 + threadIdx.x) >> 5;
    if (node >= n) return;
    int lane = threadIdx.x & 31;
    int beg = off[node], end = off[node + 1];
    float4 acc = make_float4(0.f, 0.f, 0.f, 0.f);

    if (!wt) {
        for (int base = beg; base < end; base += 32) {
            int m = end - base;
            int nb = 0;
            if (lane < m) nb = __ldg(&adj[base + lane]);
            int iters = m < 32 ? m : 32;
#pragma unroll 8
            for (int j = 0; j < iters; j++) {
                int id = __shfl_sync(0xffffffffu, nb, j);
                float4 v = *(const float4*)&X[(size_t)id * HID + lane * 4];
                acc.x += v.x; acc.y += v.y; acc.z += v.z; acc.w += v.w;
            }
        }
    } else {
        float dd = __ldg(&dinv[node]);
        float4 selfv = *(const float4*)&X[(size_t)node * HID + lane * 4];
        for (int base = beg; base < end; base += 32) {
            int m = end - base;
            int nb = 0; float w = 0.f;
            if (lane < m) {
                nb = __ldg(&adj[base + lane]);
                w = __ldg(&dinv[nb]);
            }
            int iters = m < 32 ? m : 32;
#pragma unroll 8
            for (int j = 0; j < iters; j++) {
                int id = __shfl_sync(0xffffffffu, nb, j);
                float wj = __shfl_sync(0xffffffffu, w, j);
                float4 v = *(const float4*)&X[(size_t)id * HID + lane * 4];
                acc.x = fmaf(wj, v.x, acc.x);
                acc.y = fmaf(wj, v.y, acc.y);
                acc.z = fmaf(wj, v.z, acc.z);
                acc.w = fmaf(wj, v.w, acc.w);
            }
        }
        acc.x = dd * (acc.x + dd * selfv.x);
        acc.y = dd * (acc.y + dd * selfv.y);
        acc.z = dd * (acc.z + dd * selfv.z);
        acc.w = dd * (acc.w + dd * selfv.w);
    }
    *(float4*)&OUT[(size_t)node * HID + lane * 4] = acc;
}

// ------------------------- weight bf16 split -----------------------------------
__global__ void tsplit_k(const float* __restrict__ sWl, const float* __restrict__ sWr,
                         const float* __restrict__ Wf,  const float* __restrict__ Wg,
                         const float* __restrict__ rWl, const float* __restrict__ rWr,
                         __nv_bfloat16* __restrict__ oh, __nv_bfloat16* __restrict__ ol)
{
    int gid = blockIdx.x * blockDim.x + threadIdx.x;
    if (gid >= 12 * 16384) return;
    int mat = gid >> 14;
    int e = gid & 16383;
    int l = mat / 6, m6 = mat % 6;
    const float* W;
    switch (m6) {
        case 0: W = sWl; break; case 1: W = sWr; break; case 2: W = Wf; break;
        case 3: W = Wg;  break; case 4: W = rWl; break; default: W = rWr; break;
    }
    W += l * 16384;
    float v = W[e];
    __nv_bfloat16 h = __float2bfloat16(v);
    oh[gid] = h;
    ol[gid] = __float2bfloat16(v - __bfloat162float(h));
}

__global__ void bias_k(const float* __restrict__ sbl, const float* __restrict__ bf,
                       const float* __restrict__ br,  const float* __restrict__ rbl,
                       float* __restrict__ bm, float* __restrict__ bs)
{
    int i = threadIdx.x;
    bm[i] = sbl[i] + bf[i] + br[i];
    bs[i] = rbl[i];
}

// ------------------------- fused mma.sync bf16-split GEMM ----------------------
#define A_STRIDE 40
#define B_STRIDE 136

struct GemmJob {
    const float* X0; const float* X1; const float* X2; const float* X3;
    const float* rs0;
    const __nv_bfloat16* Wh; const __nv_bfloat16* Wl;
    const float* bias; float* Y; int n; int nsrc; int block0;
};

__global__ __launch_bounds__(256) void gemm_fused_k(GemmJob ja, GemmJob jb)
{
    __shared__ __nv_bfloat16 sAh[128][A_STRIDE];
    __shared__ __nv_bfloat16 sAl[128][A_STRIDE];
    __shared__ __nv_bfloat16 sBh[32][B_STRIDE];
    __shared__ __nv_bfloat16 sBl[32][B_STRIDE];

    bool second = (blockIdx.x >= jb.block0);
    const float* X0 = second ? jb.X0 : ja.X0;
    const float* X1 = second ? jb.X1 : ja.X1;
    const float* X2 = second ? jb.X2 : ja.X2;
    const float* X3 = second ? jb.X3 : ja.X3;
    const float* rs0 = second ? jb.rs0 : ja.rs0;
    const __nv_bfloat16* Wh = second ? jb.Wh : ja.Wh;
    const __nv_bfloat16* Wl = second ? jb.Wl : ja.Wl;
    const float* bias = second ? jb.bias : ja.bias;
    float* Y = second ? jb.Y : ja.Y;
    int n = second ? jb.n : ja.n;
    int nsrc = second ? jb.nsrc : ja.nsrc;
    int row0 = (blockIdx.x - (second ? jb.block0 : ja.block0)) * 128;

    int tid = threadIdx.x, wid = tid >> 5, lane = tid & 31;
    int wm = (wid >> 2) * 64;
    int wn = (wid & 3) * 32;

    const float* Xs_[4] = {X0, X1, X2, X3};

    float acc[4][4][4];
#pragma unroll
    for (int i = 0; i < 4; i++)
#pragma unroll
        for (int j = 0; j < 4; j++)
#pragma unroll
            for (int q = 0; q < 4; q++) acc[i][j][q] = 0.0f;

    uint32_t aHiB = smem_u32(&sAh[0][0]);
    uint32_t aLoB = smem_u32(&sAl[0][0]);
    uint32_t bHiB = smem_u32(&sBh[0][0]);
    uint32_t bLoB = smem_u32(&sBl[0][0]);

    const int NCH = nsrc * 4;
    for (int ks = 0; ks < NCH; ks++) {
        int s = ks >> 2, kb = ks & 3;
        const float* Xp = Xs_[s];
        const __nv_bfloat16* whp = Wh + s * 16384;
        const __nv_bfloat16* wlp = Wl + s * 16384;
        __syncthreads();
#pragma unroll
        for (int u = 0; u < 4; u++) {
            int slot = tid + u * 256;
            int r = slot >> 3, c4 = (slot & 7) * 4;
            int gr = row0 + r;
            float4 v = make_float4(0.f, 0.f, 0.f, 0.f);
            if (gr < n) {
                v = *(const float4*)&Xp[(size_t)gr * HID + kb * 32 + c4];
                if (s == 0) { float t = rs0[gr]; v.x *= t; v.y *= t; v.z *= t; v.w *= t; }
            }
            __nv_bfloat16 hx = __float2bfloat16(v.x), hy = __float2bfloat16(v.y);
            __nv_bfloat16 hz = __float2bfloat16(v.z), hw = __float2bfloat16(v.w);
            __nv_bfloat162 h01; h01.x = hx; h01.y = hy;
            __nv_bfloat162 h23; h23.x = hz; h23.y = hw;
            __nv_bfloat162 l01, l23;
            l01.x = __float2bfloat16(v.x - __bfloat162float(hx));
            l01.y = __float2bfloat16(v.y - __bfloat162float(hy));
            l23.x = __float2bfloat16(v.z - __bfloat162float(hz));
            l23.y = __float2bfloat16(v.w - __bfloat162float(hw));
            *(__nv_bfloat162*)&sAh[r][c4]     = h01;
            *(__nv_bfloat162*)&sAh[r][c4 + 2] = h23;
            *(__nv_bfloat162*)&sAl[r][c4]     = l01;
            *(__nv_bfloat162*)&sAl[r][c4 + 2] = l23;
        }
#pragma unroll
        for (int u = 0; u < 2; u++) {
            int slot = tid + u * 256;
            int r = slot >> 4, c8 = (slot & 15) * 8;
            int go = (kb * 32 + r) * 128 + c8;
            *(uint4*)&sBh[r][c8] = *(const uint4*)&whp[go];
            *(uint4*)&sBl[r][c8] = *(const uint4*)&wlp[go];
        }
        __syncthreads();

#pragma unroll
        for (int kk = 0; kk < 32; kk += 16) {
            uint32_t ah[4][4], al[4][4], bh[4][2], bl[4][2];
            int arow = (lane & 15), acolh = kk + (lane >> 4) * 8;
#pragma unroll
            for (int mi = 0; mi < 4; mi++) {
                uint32_t off = ((wm + mi * 16 + arow) * A_STRIDE + acolh) * 2;
                ldsm_x4(ah[mi], aHiB + off);
                ldsm_x4(al[mi], aLoB + off);
            }
            int brow = kk + (lane & 15);
#pragma unroll
            for (int ni = 0; ni < 2; ni++) {
                uint32_t off = (brow * B_STRIDE + wn + ni * 16 + (lane >> 4) * 8) * 2;
                uint32_t t[4];
                ldsm_x4_t(t, bHiB + off);
                bh[2 * ni][0] = t[0]; bh[2 * ni][1] = t[1];
                bh[2 * ni + 1][0] = t[2]; bh[2 * ni + 1][1] = t[3];
                ldsm_x4_t(t, bLoB + off);
                bl[2 * ni][0] = t[0]; bl[2 * ni][1] = t[1];
                bl[2 * ni + 1][0] = t[2]; bl[2 * ni + 1][1] = t[3];
            }
#pragma unroll
            for (int mi = 0; mi < 4; mi++)
#pragma unroll
                for (int nj = 0; nj < 4; nj++) {
                    mma16816(acc[mi][nj], ah[mi], bh[nj]);
                    mma16816(acc[mi][nj], al[mi], bh[nj]);
                    mma16816(acc[mi][nj], ah[mi], bl[nj]);
                }
        }
    }

    int gid = lane >> 2, tig = lane & 3;
#pragma unroll
    for (int mi = 0; mi < 4; mi++) {
        int r0 = row0 + wm + mi * 16 + gid;
        int r1 = r0 + 8;
#pragma unroll
        for (int nj = 0; nj < 4; nj++) {
            int c = wn + nj * 8 + tig * 2;
            float b0 = __ldg(&bias[c]), b1 = __ldg(&bias[c + 1]);
            if (r0 < n) {
                float2 o;
                o.x = fmaxf(acc[mi][nj][0] + b0, 0.f);
                o.y = fmaxf(acc[mi][nj][1] + b1, 0.f);
                *(float2*)&Y[(size_t)r0 * HID + c] = o;
            }
            if (r1 < n) {
                float2 o;
                o.x = fmaxf(acc[mi][nj][2] + b0, 0.f);
                o.y = fmaxf(acc[mi][nj][3] + b1, 0.f);
                *(float2*)&Y[(size_t)r1 * HID + c] = o;
            }
        }
    }
}

// ------------------------- classifier -----------------------------------------
__global__ __launch_bounds__(256) void classifier_k(
    const int* __restrict__ ls, const int* __restrict__ ld,
    const float* __restrict__ XS, const float* __restrict__ XM,
    float* __restrict__ out, int E)
{
    int e = (blockIdx.x * blockDim.x + threadIdx.x) >> 5;
    if (e >= E) return;
    int lane = threadIdx.x & 31;
    int s = __ldg(&ls[e]);
    int d = __ldg(&ld[e]);
    float4 a = *(const float4*)&XS[(size_t)s * HID + lane * 4];
    float4 b = *(const float4*)&XM[(size_t)d * HID + lane * 4];
    float p = a.x * b.x + a.y * b.y + a.z * b.z + a.w * b.w;
#pragma unroll
    for (int o = 16; o > 0; o >>= 1) p += __shfl_xor_sync(0xffffffffu, p, o);
    if (lane == 0) out[e] = p;
}

// ------------------------- launch ---------------------------------------------
extern "C" void kernel_launch(void* const* d_in, const int* in_sizes, int n_in,
                              void* d_out, int out_size)
{
    const int*   s2m_src   = (const int*)d_in[0];
    const int*   s2m_dst   = (const int*)d_in[1];
    const int*   m2m_src   = (const int*)d_in[2];
    const int*   m2m_dst   = (const int*)d_in[3];
    const int*   label_src = (const int*)d_in[4];
    const int*   label_dst = (const int*)d_in[5];
    const float* srna_emb  = (const float*)d_in[6];
    const float* mrna_emb  = (const float*)d_in[7];
    const float* sage_s2m_Wl = (const float*)d_in[8];
    const float* sage_s2m_bl = (const float*)d_in[9];
    const float* sage_s2m_Wr = (const float*)d_in[10];
    const float* sage_rev_Wl = (const float*)d_in[11];
    const float* sage_rev_bl = (const float*)d_in[12];
    const float* sage_rev_Wr = (const float*)d_in[13];
    const float* gcn_m2m_W   = (const float*)d_in[14];
    const float* gcn_m2m_b   = (const float*)d_in[15];
    const float* gcn_rev_W   = (const float*)d_in[16];
    const float* gcn_rev_b   = (const float*)d_in[17];
    float* out = (float*)d_out;

    float *aggm, *aggf, *aggr, *xm0, *xm1, *aggs, *xs0, *xs1;
    float *cinvm, *cinvs, *dinvf, *dinvr, *bm, *bs;
    __nv_bfloat16 *wth, *wtl;
    int *cnt, *cur, *off, *adjA, *adjB, *adjC, *adjD;
    cudaGetSymbolAddress((void**)&aggm, g_aggm);
    cudaGetSymbolAddress((void**)&aggf, g_aggf);
    cudaGetSymbolAddress((void**)&aggr, g_aggr);
    cudaGetSymbolAddress((void**)&xm0,  g_xm0);
    cudaGetSymbolAddress((void**)&xm1,  g_xm1);
    cudaGetSymbolAddress((void**)&aggs, g_aggs);
    cudaGetSymbolAddress((void**)&xs0,  g_xs0);
    cudaGetSymbolAddress((void**)&xs1,  g_xs1);
    cudaGetSymbolAddress((void**)&cinvm, g_cinvm);
    cudaGetSymbolAddress((void**)&cinvs, g_cinvs);
    cudaGetSymbolAddress((void**)&dinvf, g_dinvf);
    cudaGetSymbolAddress((void**)&dinvr, g_dinvr);
    cudaGetSymbolAddress((void**)&wth, g_wt_hi);
    cudaGetSymbolAddress((void**)&wtl, g_wt_lo);
    cudaGetSymbolAddress((void**)&bm,  g_bias_m);
    cudaGetSymbolAddress((void**)&bs,  g_bias_s);
    cudaGetSymbolAddress((void**)&cnt, g_cnt);
    cudaGetSymbolAddress((void**)&cur, g_cur);
    cudaGetSymbolAddress((void**)&off, g_off);
    cudaGetSymbolAddress((void**)&adjA, g_adjA);
    cudaGetSymbolAddress((void**)&adjB, g_adjB);
    cudaGetSymbolAddress((void**)&adjC, g_adjC);
    cudaGetSymbolAddress((void**)&adjD, g_adjD);

    // ---- weight prep + biases ----
    tsplit_k<<<(12 * 16384 + 255) / 256, 256>>>(sage_s2m_Wl, sage_s2m_Wr, gcn_m2m_W,
                                                gcn_rev_W, sage_rev_Wl, sage_rev_Wr, wth, wtl);
    bias_k<<<1, 256>>>(sage_s2m_bl, gcn_m2m_b, gcn_rev_b, sage_rev_bl, bm, bs);

    // ---- CSR build (fused) ----
    cudaMemsetAsync(cnt, 0, CNT_TOT * sizeof(int));
    cudaMemsetAsync(cur, 0, CNT_TOT * sizeof(int));
    count_all_k<<<4096, 256>>>(s2m_src, s2m_dst, m2m_src, m2m_dst, cnt);
    scan4_k<<<4, 1024>>>(cnt, off);
    finalize_all_k<<<(N_MRNA + 255) / 256, 256>>>(cnt, cinvm, cinvs, dinvf, dinvr);
    fill_all_k<<<4096, 256>>>(s2m_src, s2m_dst, m2m_src, m2m_dst,
                              off, cur, adjA, adjB, adjC, adjD);

    const float* xs = srna_emb;
    const float* xm = mrna_emb;
    float* xm_bufs[2] = {xm0, xm1};
    float* xs_bufs[2] = {xs0, xs1};

    const int gm = (N_MRNA + 127) / 128;       // 782
    const int gs = (N_SRNA + 127) / 128;       // 157
    const int gbm = (N_MRNA + 7) / 8;          // blocks per m-gather: 12500
    const int gbs = (N_SRNA + 7) / 8;          // blocks per s-gather: 2500
    const int gather_grid = gbm * 3 + gbs;     // 40000

    for (int l = 0; l < 2; l++) {
        const __nv_bfloat16* wth_m = wth + (size_t)(l * 6 + 0) * 16384;
        const __nv_bfloat16* wtl_m = wtl + (size_t)(l * 6 + 0) * 16384;
        const __nv_bfloat16* wth_s = wth + (size_t)(l * 6 + 4) * 16384;
        const __nv_bfloat16* wtl_s = wtl + (size_t)(l * 6 + 4) * 16384;

        GathJob ga = { off + F_A, adjA, xs, nullptr, aggm, N_MRNA, 0 };
        GathJob gb = { off + F_B, adjB, xm, nullptr, aggs, N_SRNA, gbm };
        GathJob gc = { off + F_C, adjC, xm, dinvf,   aggf, N_MRNA, gbm + gbs };
        GathJob gd = { off + F_D, adjD, xm, dinvr,   aggr, N_MRNA, 2 * gbm + gbs };
        gather_all_k<<<gather_grid, 256>>>(ga, gb, gc, gd);

        GemmJob jm = { aggm, xm, aggf, aggr, cinvm, wth_m, wtl_m,
                       bm + l * 128, xm_bufs[l], N_MRNA, 4, 0 };
        GemmJob js = { aggs, xs, nullptr, nullptr, cinvs, wth_s, wtl_s,
                       bs + l * 128, xs_bufs[l], N_SRNA, 2, gm };
        gemm_fused_k<<<gm + gs, 256>>>(jm, js);

        xm = xm_bufs[l];
        xs = xs_bufs[l];
    }

    classifier_k<<<(E_LBL * 32 + 255) / 256, 256>>>(label_src, label_dst, xs, xm, out, E_LBL);
}

// round 15
// speedup vs baseline: 1.8388x; 1.0220x over previous
#include <cuda_runtime.h>
#include <cuda_bf16.h>
#include <cstdint>

#define N_SRNA 20000
#define N_MRNA 100000
#define HID    128
#define E_S2M  1000000
#define E_M2M  2000000
#define E_LBL  500000

#define CNT_TOT (3*N_MRNA + N_SRNA)
// segment layout in cnt/cur/off: A [0,N_MRNA), C [N_MRNA,2N), D [2N,3N), B [3N,3N+N_SRNA)
#define O_A 0
#define O_C N_MRNA
#define O_D (2*N_MRNA)
#define O_B (3*N_MRNA)

// ------------------------- scratch (module-static) ----------------------------
__device__ float g_aggm[N_MRNA*HID];
__device__ float g_aggf[N_MRNA*HID];
__device__ float g_aggr[N_MRNA*HID];
__device__ float g_xm0 [N_MRNA*HID];
__device__ float g_xm1 [N_MRNA*HID];
__device__ float g_aggs[N_SRNA*HID];
__device__ float g_xs0 [N_SRNA*HID];
__device__ float g_xs1 [N_SRNA*HID];

__device__ float g_cinvm[N_MRNA];
__device__ float g_cinvs[N_SRNA];
__device__ float g_dinvf[N_MRNA];
__device__ float g_dinvr[N_MRNA];

__device__ __nv_bfloat16 g_wt_hi[12*16384];
__device__ __nv_bfloat16 g_wt_lo[12*16384];
__device__ float g_bias_m[2*128];
__device__ float g_bias_s[2*128];

__device__ int g_cnt[CNT_TOT];
__device__ int g_cur[CNT_TOT + 4];   // tail 4 ints = per-segment allocation counters
__device__ int g_off[CNT_TOT];
__device__ int g_adjA[E_S2M];
__device__ int g_adjB[E_S2M];
__device__ int g_adjC[E_M2M];
__device__ int g_adjD[E_M2M];

// ------------------------- helpers --------------------------------------------
__device__ __forceinline__ uint32_t smem_u32(const void* p) {
    uint32_t a;
    asm("{ .reg .u64 t; cvta.to.shared.u64 t, %1; cvt.u32.u64 %0, t; }" : "=r"(a) : "l"(p));
    return a;
}
__device__ __forceinline__ void ldsm_x4(uint32_t* r, uint32_t addr) {
    asm volatile("ldmatrix.sync.aligned.m8n8.x4.shared.b16 {%0,%1,%2,%3}, [%4];"
        : "=r"(r[0]), "=r"(r[1]), "=r"(r[2]), "=r"(r[3]) : "r"(addr));
}
__device__ __forceinline__ void ldsm_x4_t(uint32_t* r, uint32_t addr) {
    asm volatile("ldmatrix.sync.aligned.m8n8.x4.trans.shared.b16 {%0,%1,%2,%3}, [%4];"
        : "=r"(r[0]), "=r"(r[1]), "=r"(r[2]), "=r"(r[3]) : "r"(addr));
}
__device__ __forceinline__ void mma16816(float* c, const uint32_t* a, const uint32_t* b) {
    asm volatile(
        "mma.sync.aligned.m16n8k16.row.col.f32.bf16.bf16.f32 "
        "{%0,%1,%2,%3}, {%4,%5,%6,%7}, {%8,%9}, {%0,%1,%2,%3};"
        : "+f"(c[0]), "+f"(c[1]), "+f"(c[2]), "+f"(c[3])
        : "r"(a[0]), "r"(a[1]), "r"(a[2]), "r"(a[3]), "r"(b[0]), "r"(b[1]));
}

// ------------------------- fused count -----------------------------------------
#define E_TOT (2*E_S2M + 2*E_M2M)

__global__ void count_all_k(const int* __restrict__ s2m_src, const int* __restrict__ s2m_dst,
                            const int* __restrict__ m2m_src, const int* __restrict__ m2m_dst,
                            int* __restrict__ cnt)
{
    int i = blockIdx.x * blockDim.x + threadIdx.x;
    int stride = gridDim.x * blockDim.x;
    for (; i < E_TOT; i += stride) {
        if (i < E_S2M)                    atomicAdd(&cnt[O_A + s2m_dst[i]], 1);
        else if (i < 2*E_S2M)             atomicAdd(&cnt[O_B + s2m_src[i - E_S2M]], 1);
        else if (i < 2*E_S2M + E_M2M)     atomicAdd(&cnt[O_C + m2m_dst[i - 2*E_S2M]], 1);
        else                              atomicAdd(&cnt[O_D + m2m_src[i - 2*E_S2M - E_M2M]], 1);
    }
}

// ------------------------- offsets (warp-agg atomic alloc) + finalize ----------
// Replaces the serial 4-block scan. Each node gets a private contiguous range
// [off[i], off[i]+cnt[i]) in its segment's edge array; ranges need not be
// monotonic. Segment boundaries are 32-divisible, so no warp straddles.
__global__ void offsets_fin_k(const int* __restrict__ cnt, int* __restrict__ off,
                              int* __restrict__ gctr,
                              float* __restrict__ cinvm, float* __restrict__ cinvs,
                              float* __restrict__ dinvf, float* __restrict__ dinvr)
{
    int i = blockIdx.x * blockDim.x + threadIdx.x;
    if (i >= CNT_TOT) return;
    int lane = threadIdx.x & 31;
    int v = cnt[i];
    int seg = (i < N_MRNA) ? 0 : (i < 2*N_MRNA) ? 1 : (i < 3*N_MRNA) ? 2 : 3;
    int x = v;
#pragma unroll
    for (int d = 1; d < 32; d <<= 1) {
        int y = __shfl_up_sync(0xffffffffu, x, d);
        if (lane >= d) x += y;
    }
    int excl = x - v;
    int total = __shfl_sync(0xffffffffu, x, 31);
    int base = 0;
    if (lane == 0) base = atomicAdd(&gctr[seg], total);
    base = __shfl_sync(0xffffffffu, base, 0);
    off[i] = base + excl;

    if (seg == 0)      cinvm[i]             = 1.0f / fmaxf((float)v, 1.0f);
    else if (seg == 1) dinvf[i - N_MRNA]    = rsqrtf((float)v + 1.0f);
    else if (seg == 2) dinvr[i - 2*N_MRNA]  = rsqrtf((float)v + 1.0f);
    else               cinvs[i - 3*N_MRNA]  = 1.0f / fmaxf((float)v, 1.0f);
}

// ------------------------- fused fill ------------------------------------------
__global__ void fill_all_k(const int* __restrict__ s2m_src, const int* __restrict__ s2m_dst,
                           const int* __restrict__ m2m_src, const int* __restrict__ m2m_dst,
                           const int* __restrict__ off, int* __restrict__ cur,
                           int* __restrict__ adjA, int* __restrict__ adjB,
                           int* __restrict__ adjC, int* __restrict__ adjD)
{
    int i = blockIdx.x * blockDim.x + threadIdx.x;
    int stride = gridDim.x * blockDim.x;
    for (; i < E_TOT; i += stride) {
        if (i < E_S2M) {
            int k = s2m_dst[i];
            int pos = off[O_A + k] + atomicAdd(&cur[O_A + k], 1);
            adjA[pos] = s2m_src[i];
        } else if (i < 2*E_S2M) {
            int j = i - E_S2M;
            int k = s2m_src[j];
            int pos = off[O_B + k] + atomicAdd(&cur[O_B + k], 1);
            adjB[pos] = s2m_dst[j];
        } else if (i < 2*E_S2M + E_M2M) {
            int j = i - 2*E_S2M;
            int k = m2m_dst[j];
            int pos = off[O_C + k] + atomicAdd(&cur[O_C + k], 1);
            adjC[pos] = m2m_src[j];
        } else {
            int j = i - 2*E_S2M - E_M2M;
            int k = m2m_src[j];
            int pos = off[O_D + k] + atomicAdd(&cur[O_D + k], 1);
            adjD[pos] = m2m_dst[j];
        }
    }
}

// ------------------------- fused gather (4 jobs, 1 launch) ---------------------
struct GathJob {
    const int* off; const int* cnt; const int* adj; const float* X;
    const float* dinv; float* OUT; int n; int block0;
};

__global__ __launch_bounds__(256) void gather_all_k(GathJob j0, GathJob j1,
                                                    GathJob j2, GathJob j3)
{
    int b = blockIdx.x;
    const int* off; const int* cntp; const int* adj; const float* X;
    const float* dinv; float* OUT; int n; int lb; bool wt;
    if (b >= j3.block0)      { off=j3.off; cntp=j3.cnt; adj=j3.adj; X=j3.X; dinv=j3.dinv; OUT=j3.OUT; n=j3.n; lb=b-j3.block0; wt=true; }
    else if (b >= j2.block0) { off=j2.off; cntp=j2.cnt; adj=j2.adj; X=j2.X; dinv=j2.dinv; OUT=j2.OUT; n=j2.n; lb=b-j2.block0; wt=true; }
    else if (b >= j1.block0) { off=j1.off; cntp=j1.cnt; adj=j1.adj; X=j1.X; dinv=j1.dinv; OUT=j1.OUT; n=j1.n; lb=b-j1.block0; wt=false; }
    else                     { off=j0.off; cntp=j0.cnt; adj=j0.adj; X=j0.X; dinv=j0.dinv; OUT=j0.OUT; n=j0.n; lb=b-j0.block0; wt=false; }

    int node = (lb * 256 + threadIdx.x) >> 5;
    if (node >= n) return;
    int lane = threadIdx.x & 31;
    int beg = __ldg(&off[node]);
    int end = beg + __ldg(&cntp[node]);
    float4 acc = make_float4(0.f, 0.f, 0.f, 0.f);

    if (!wt) {
        for (int base = beg; base < end; base += 32) {
            int m = end - base;
            int nb = 0;
            if (lane < m) nb = __ldg(&adj[base + lane]);
            int iters = m < 32 ? m : 32;
#pragma unroll 8
            for (int j = 0; j < iters; j++) {
                int id = __shfl_sync(0xffffffffu, nb, j);
                float4 v = *(const float4*)&X[(size_t)id * HID + lane * 4];
                acc.x += v.x; acc.y += v.y; acc.z += v.z; acc.w += v.w;
            }
        }
    } else {
        float dd = __ldg(&dinv[node]);
        float4 selfv = *(const float4*)&X[(size_t)node * HID + lane * 4];
        for (int base = beg; base < end; base += 32) {
            int m = end - base;
            int nb = 0; float w = 0.f;
            if (lane < m) {
                nb = __ldg(&adj[base + lane]);
                w = __ldg(&dinv[nb]);
            }
            int iters = m < 32 ? m : 32;
#pragma unroll 8
            for (int j = 0; j < iters; j++) {
                int id = __shfl_sync(0xffffffffu, nb, j);
                float wj = __shfl_sync(0xffffffffu, w, j);
                float4 v = *(const float4*)&X[(size_t)id * HID + lane * 4];
                acc.x = fmaf(wj, v.x, acc.x);
                acc.y = fmaf(wj, v.y, acc.y);
                acc.z = fmaf(wj, v.z, acc.z);
                acc.w = fmaf(wj, v.w, acc.w);
            }
        }
        acc.x = dd * (acc.x + dd * selfv.x);
        acc.y = dd * (acc.y + dd * selfv.y);
        acc.z = dd * (acc.z + dd * selfv.z);
        acc.w = dd * (acc.w + dd * selfv.w);
    }
    *(float4*)&OUT[(size_t)node * HID + lane * 4] = acc;
}

// ------------------------- weight bf16 split -----------------------------------
__global__ void tsplit_k(const float* __restrict__ sWl, const float* __restrict__ sWr,
                         const float* __restrict__ Wf,  const float* __restrict__ Wg,
                         const float* __restrict__ rWl, const float* __restrict__ rWr,
                         __nv_bfloat16* __restrict__ oh, __nv_bfloat16* __restrict__ ol)
{
    int gid = blockIdx.x * blockDim.x + threadIdx.x;
    if (gid >= 12 * 16384) return;
    int mat = gid >> 14;
    int e = gid & 16383;
    int l = mat / 6, m6 = mat % 6;
    const float* W;
    switch (m6) {
        case 0: W = sWl; break; case 1: W = sWr; break; case 2: W = Wf; break;
        case 3: W = Wg;  break; case 4: W = rWl; break; default: W = rWr; break;
    }
    W += l * 16384;
    float v = W[e];
    __nv_bfloat16 h = __float2bfloat16(v);
    oh[gid] = h;
    ol[gid] = __float2bfloat16(v - __bfloat162float(h));
}

__global__ void bias_k(const float* __restrict__ sbl, const float* __restrict__ bf,
                       const float* __restrict__ br,  const float* __restrict__ rbl,
                       float* __restrict__ bm, float* __restrict__ bs)
{
    int i = threadIdx.x;
    bm[i] = sbl[i] + bf[i] + br[i];
    bs[i] = rbl[i];
}

// ------------------------- fused mma.sync bf16-split GEMM ----------------------
#define A_STRIDE 40
#define B_STRIDE 136

struct GemmJob {
    const float* X0; const float* X1; const float* X2; const float* X3;
    const float* rs0;
    const __nv_bfloat16* Wh; const __nv_bfloat16* Wl;
    const float* bias; float* Y; int n; int nsrc; int block0;
};

__global__ __launch_bounds__(256) void gemm_fused_k(GemmJob ja, GemmJob jb)
{
    __shared__ __nv_bfloat16 sAh[128][A_STRIDE];
    __shared__ __nv_bfloat16 sAl[128][A_STRIDE];
    __shared__ __nv_bfloat16 sBh[32][B_STRIDE];
    __shared__ __nv_bfloat16 sBl[32][B_STRIDE];

    bool second = (blockIdx.x >= jb.block0);
    const float* X0 = second ? jb.X0 : ja.X0;
    const float* X1 = second ? jb.X1 : ja.X1;
    const float* X2 = second ? jb.X2 : ja.X2;
    const float* X3 = second ? jb.X3 : ja.X3;
    const float* rs0 = second ? jb.rs0 : ja.rs0;
    const __nv_bfloat16* Wh = second ? jb.Wh : ja.Wh;
    const __nv_bfloat16* Wl = second ? jb.Wl : ja.Wl;
    const float* bias = second ? jb.bias : ja.bias;
    float* Y = second ? jb.Y : ja.Y;
    int n = second ? jb.n : ja.n;
    int nsrc = second ? jb.nsrc : ja.nsrc;
    int row0 = (blockIdx.x - (second ? jb.block0 : ja.block0)) * 128;

    int tid = threadIdx.x, wid = tid >> 5, lane = tid & 31;
    int wm = (wid >> 2) * 64;
    int wn = (wid & 3) * 32;

    const float* Xs_[4] = {X0, X1, X2, X3};

    float acc[4][4][4];
#pragma unroll
    for (int i = 0; i < 4; i++)
#pragma unroll
        for (int j = 0; j < 4; j++)
#pragma unroll
            for (int q = 0; q < 4; q++) acc[i][j][q] = 0.0f;

    uint32_t aHiB = smem_u32(&sAh[0][0]);
    uint32_t aLoB = smem_u32(&sAl[0][0]);
    uint32_t bHiB = smem_u32(&sBh[0][0]);
    uint32_t bLoB = smem_u32(&sBl[0][0]);

    const int NCH = nsrc * 4;
    for (int ks = 0; ks < NCH; ks++) {
        int s = ks >> 2, kb = ks & 3;
        const float* Xp = Xs_[s];
        const __nv_bfloat16* whp = Wh + s * 16384;
        const __nv_bfloat16* wlp = Wl + s * 16384;
        __syncthreads();
#pragma unroll
        for (int u = 0; u < 4; u++) {
            int slot = tid + u * 256;
            int r = slot >> 3, c4 = (slot & 7) * 4;
            int gr = row0 + r;
            float4 v = make_float4(0.f, 0.f, 0.f, 0.f);
            if (gr < n) {
                v = *(const float4*)&Xp[(size_t)gr * HID + kb * 32 + c4];
                if (s == 0) { float t = rs0[gr]; v.x *= t; v.y *= t; v.z *= t; v.w *= t; }
            }
            __nv_bfloat16 hx = __float2bfloat16(v.x), hy = __float2bfloat16(v.y);
            __nv_bfloat16 hz = __float2bfloat16(v.z), hw = __float2bfloat16(v.w);
            __nv_bfloat162 h01; h01.x = hx; h01.y = hy;
            __nv_bfloat162 h23; h23.x = hz; h23.y = hw;
            __nv_bfloat162 l01, l23;
            l01.x = __float2bfloat16(v.x - __bfloat162float(hx));
            l01.y = __float2bfloat16(v.y - __bfloat162float(hy));
            l23.x = __float2bfloat16(v.z - __bfloat162float(hz));
            l23.y = __float2bfloat16(v.w - __bfloat162float(hw));
            *(__nv_bfloat162*)&sAh[r][c4]     = h01;
            *(__nv_bfloat162*)&sAh[r][c4 + 2] = h23;
            *(__nv_bfloat162*)&sAl[r][c4]     = l01;
            *(__nv_bfloat162*)&sAl[r][c4 + 2] = l23;
        }
#pragma unroll
        for (int u = 0; u < 2; u++) {
            int slot = tid + u * 256;
            int r = slot >> 4, c8 = (slot & 15) * 8;
            int go = (kb * 32 + r) * 128 + c8;
            *(uint4*)&sBh[r][c8] = *(const uint4*)&whp[go];
            *(uint4*)&sBl[r][c8] = *(const uint4*)&wlp[go];
        }
        __syncthreads();

#pragma unroll
        for (int kk = 0; kk < 32; kk += 16) {
            uint32_t ah[4][4], al[4][4], bh[4][2], bl[4][2];
            int arow = (lane & 15), acolh = kk + (lane >> 4) * 8;
#pragma unroll
            for (int mi = 0; mi < 4; mi++) {
                uint32_t off = ((wm + mi * 16 + arow) * A_STRIDE + acolh) * 2;
                ldsm_x4(ah[mi], aHiB + off);
                ldsm_x4(al[mi], aLoB + off);
            }
            int brow = kk + (lane & 15);
#pragma unroll
            for (int ni = 0; ni < 2; ni++) {
                uint32_t off = (brow * B_STRIDE + wn + ni * 16 + (lane >> 4) * 8) * 2;
                uint32_t t[4];
                ldsm_x4_t(t, bHiB + off);
                bh[2 * ni][0] = t[0]; bh[2 * ni][1] = t[1];
                bh[2 * ni + 1][0] = t[2]; bh[2 * ni + 1][1] = t[3];
                ldsm_x4_t(t, bLoB + off);
                bl[2 * ni][0] = t[0]; bl[2 * ni][1] = t[1];
                bl[2 * ni + 1][0] = t[2]; bl[2 * ni + 1][1] = t[3];
            }
#pragma unroll
            for (int mi = 0; mi < 4; mi++)
#pragma unroll
                for (int nj = 0; nj < 4; nj++) {
                    mma16816(acc[mi][nj], ah[mi], bh[nj]);
                    mma16816(acc[mi][nj], al[mi], bh[nj]);
                    mma16816(acc[mi][nj], ah[mi], bl[nj]);
                }
        }
    }

    int gid = lane >> 2, tig = lane & 3;
#pragma unroll
    for (int mi = 0; mi < 4; mi++) {
        int r0 = row0 + wm + mi * 16 + gid;
        int r1 = r0 + 8;
#pragma unroll
        for (int nj = 0; nj < 4; nj++) {
            int c = wn + nj * 8 + tig * 2;
            float b0 = __ldg(&bias[c]), b1 = __ldg(&bias[c + 1]);
            if (r0 < n) {
                float2 o;
                o.x = fmaxf(acc[mi][nj][0] + b0, 0.f);
                o.y = fmaxf(acc[mi][nj][1] + b1, 0.f);
                *(float2*)&Y[(size_t)r0 * HID + c] = o;
            }
            if (r1 < n) {
                float2 o;
                o.x = fmaxf(acc[mi][nj][2] + b0, 0.f);
                o.y = fmaxf(acc[mi][nj][3] + b1, 0.f);
                *(float2*)&Y[(size_t)r1 * HID + c] = o;
            }
        }
    }
}

// ------------------------- classifier -----------------------------------------
__global__ __launch_bounds__(256) void classifier_k(
    const int* __restrict__ ls, const int* __restrict__ ld,
    const float* __restrict__ XS, const float* __restrict__ XM,
    float* __restrict__ out, int E)
{
    int e = (blockIdx.x * blockDim.x + threadIdx.x) >> 5;
    if (e >= E) return;
    int lane = threadIdx.x & 31;
    int s = __ldg(&ls[e]);
    int d = __ldg(&ld[e]);
    float4 a = *(const float4*)&XS[(size_t)s * HID + lane * 4];
    float4 b = *(const float4*)&XM[(size_t)d * HID + lane * 4];
    float p = a.x * b.x + a.y * b.y + a.z * b.z + a.w * b.w;
#pragma unroll
    for (int o = 16; o > 0; o >>= 1) p += __shfl_xor_sync(0xffffffffu, p, o);
    if (lane == 0) out[e] = p;
}

// ------------------------- launch ---------------------------------------------
extern "C" void kernel_launch(void* const* d_in, const int* in_sizes, int n_in,
                              void* d_out, int out_size)
{
    const int*   s2m_src   = (const int*)d_in[0];
    const int*   s2m_dst   = (const int*)d_in[1];
    const int*   m2m_src   = (const int*)d_in[2];
    const int*   m2m_dst   = (const int*)d_in[3];
    const int*   label_src = (const int*)d_in[4];
    const int*   label_dst = (const int*)d_in[5];
    const float* srna_emb  = (const float*)d_in[6];
    const float* mrna_emb  = (const float*)d_in[7];
    const float* sage_s2m_Wl = (const float*)d_in[8];
    const float* sage_s2m_bl = (const float*)d_in[9];
    const float* sage_s2m_Wr = (const float*)d_in[10];
    const float* sage_rev_Wl = (const float*)d_in[11];
    const float* sage_rev_bl = (const float*)d_in[12];
    const float* sage_rev_Wr = (const float*)d_in[13];
    const float* gcn_m2m_W   = (const float*)d_in[14];
    const float* gcn_m2m_b   = (const float*)d_in[15];
    const float* gcn_rev_W   = (const float*)d_in[16];
    const float* gcn_rev_b   = (const float*)d_in[17];
    float* out = (float*)d_out;

    float *aggm, *aggf, *aggr, *xm0, *xm1, *aggs, *xs0, *xs1;
    float *cinvm, *cinvs, *dinvf, *dinvr, *bm, *bs;
    __nv_bfloat16 *wth, *wtl;
    int *cnt, *cur, *off, *adjA, *adjB, *adjC, *adjD;
    cudaGetSymbolAddress((void**)&aggm, g_aggm);
    cudaGetSymbolAddress((void**)&aggf, g_aggf);
    cudaGetSymbolAddress((void**)&aggr, g_aggr);
    cudaGetSymbolAddress((void**)&xm0,  g_xm0);
    cudaGetSymbolAddress((void**)&xm1,  g_xm1);
    cudaGetSymbolAddress((void**)&aggs, g_aggs);
    cudaGetSymbolAddress((void**)&xs0,  g_xs0);
    cudaGetSymbolAddress((void**)&xs1,  g_xs1);
    cudaGetSymbolAddress((void**)&cinvm, g_cinvm);
    cudaGetSymbolAddress((void**)&cinvs, g_cinvs);
    cudaGetSymbolAddress((void**)&dinvf, g_dinvf);
    cudaGetSymbolAddress((void**)&dinvr, g_dinvr);
    cudaGetSymbolAddress((void**)&wth, g_wt_hi);
    cudaGetSymbolAddress((void**)&wtl, g_wt_lo);
    cudaGetSymbolAddress((void**)&bm,  g_bias_m);
    cudaGetSymbolAddress((void**)&bs,  g_bias_s);
    cudaGetSymbolAddress((void**)&cnt, g_cnt);
    cudaGetSymbolAddress((void**)&cur, g_cur);
    cudaGetSymbolAddress((void**)&off, g_off);
    cudaGetSymbolAddress((void**)&adjA, g_adjA);
    cudaGetSymbolAddress((void**)&adjB, g_adjB);
    cudaGetSymbolAddress((void**)&adjC, g_adjC);
    cudaGetSymbolAddress((void**)&adjD, g_adjD);

    // ---- weight prep + biases ----
    tsplit_k<<<(12 * 16384 + 255) / 256, 256>>>(sage_s2m_Wl, sage_s2m_Wr, gcn_m2m_W,
                                                gcn_rev_W, sage_rev_Wl, sage_rev_Wr, wth, wtl);
    bias_k<<<1, 256>>>(sage_s2m_bl, gcn_m2m_b, gcn_rev_b, sage_rev_bl, bm, bs);

    // ---- CSR build (fused; scan replaced by warp-agg atomic allocation) ----
    cudaMemsetAsync(cnt, 0, CNT_TOT * sizeof(int));
    cudaMemsetAsync(cur, 0, (CNT_TOT + 4) * sizeof(int));   // tail = segment counters
    count_all_k<<<4096, 256>>>(s2m_src, s2m_dst, m2m_src, m2m_dst, cnt);
    offsets_fin_k<<<CNT_TOT / 256, 256>>>(cnt, off, cur + CNT_TOT,
                                          cinvm, cinvs, dinvf, dinvr);
    fill_all_k<<<4096, 256>>>(s2m_src, s2m_dst, m2m_src, m2m_dst,
                              off, cur, adjA, adjB, adjC, adjD);

    const float* xs = srna_emb;
    const float* xm = mrna_emb;
    float* xm_bufs[2] = {xm0, xm1};
    float* xs_bufs[2] = {xs0, xs1};

    const int gm = (N_MRNA + 127) / 128;       // 782
    const int gs = (N_SRNA + 127) / 128;       // 157
    const int gbm = (N_MRNA + 7) / 8;          // 12500
    const int gbs = (N_SRNA + 7) / 8;          // 2500
    const int gather_grid = gbm * 3 + gbs;     // 40000

    for (int l = 0; l < 2; l++) {
        const __nv_bfloat16* wth_m = wth + (size_t)(l * 6 + 0) * 16384;
        const __nv_bfloat16* wtl_m = wtl + (size_t)(l * 6 + 0) * 16384;
        const __nv_bfloat16* wth_s = wth + (size_t)(l * 6 + 4) * 16384;
        const __nv_bfloat16* wtl_s = wtl + (size_t)(l * 6 + 4) * 16384;

        GathJob ga = { off + O_A, cnt + O_A, adjA, xs, nullptr, aggm, N_MRNA, 0 };
        GathJob gb = { off + O_B, cnt + O_B, adjB, xm, nullptr, aggs, N_SRNA, gbm };
        GathJob gc = { off + O_C, cnt + O_C, adjC, xm, dinvf,   aggf, N_MRNA, gbm + gbs };
        GathJob gd = { off + O_D, cnt + O_D, adjD, xm, dinvr,   aggr, N_MRNA, 2 * gbm + gbs };
        gather_all_k<<<gather_grid, 256>>>(ga, gb, gc, gd);

        GemmJob jm = { aggm, xm, aggf, aggr, cinvm, wth_m, wtl_m,
                       bm + l * 128, xm_bufs[l], N_MRNA, 4, 0 };
        GemmJob js = { aggs, xs, nullptr, nullptr, cinvs, wth_s, wtl_s,
                       bs + l * 128, xs_bufs[l], N_SRNA, 2, gm };
        gemm_fused_k<<<gm + gs, 256>>>(jm, js);

        xm = xm_bufs[l];
        xs = xs_bufs[l];
    }

    classifier_k<<<(E_LBL * 32 + 255) / 256, 256>>>(label_src, label_dst, xs, xm, out, E_LBL);
}